// round 14
// baseline (speedup 1.0000x reference)
#include <cuda_runtime.h>
#include <cstdint>

#define BB 32
#define AA 1024
#define DD 128
#define THR2 0.0025f
#define TMR 64   // MLP rows per block

typedef unsigned long long u64;

// Scratch (allocation-free rule: __device__ globals)
__device__ int g_cnt[BB * AA];          // per-(batch,group) member counts
__device__ int g_goff[BB * AA];         // per-(batch,group) member-list offset
__device__ int g_memlist[BB * AA + 8];  // agents counting-sorted by (batch,group); +8 pad
__device__ int g_ng[BB];                // groups per batch

__device__ __forceinline__ float gelu_exact(float x) {
    return 0.5f * x * (1.0f + erff(x * 0.70710678118654752f));
}

// ---------------------------------------------------------------------------
// Kernel 1: FUSED adjacency build + wavefront clustering (32 blocks x 1024).
// The compacted adjacency is built DIRECTLY into padded SMEM (33 words/row,
// conflict-free reads adj[tid*33+k]) — no 4MB global round-trip, no separate
// launch. Build: 4 rows/warp, word-inner ballots, f32x2 distance (exactly
// equals __fadd_rn(__fmul_rn(dx,dx), __fmul_rn(dy,dy)) lane-wise).
// Then the R13 wavefront + atomicOr member phase (measured-good) unchanged.
// SMEM: adj 132KB + scc 8KB + cnt/goff 8KB + small ~= 152.3KB dynamic.
// ---------------------------------------------------------------------------
__global__ __launch_bounds__(1024, 1)
void scan_kernel(const float* __restrict__ coords, const int* __restrict__ mask,
                 float* __restrict__ out_mask,   // may be null
                 float* __restrict__ out_a2g)    // may be null
{
    extern __shared__ unsigned char sraw[];
    uint32_t* adj    = (uint32_t*)sraw;             // AA*33 (padded rows)
    float2*   scc    = (float2*)(adj + AA * 33);    // AA compacted coords
    int*      s_cnt  = (int*)(scc + AA);            // AA
    int*      s_goff = s_cnt + AA;                  // AA
    uint32_t* svw    = (uint32_t*)(s_goff + AA);    // 32
    uint32_t* sS     = svw + 32;                    // 32 starter bits (compacted)
    uint32_t* sR     = sS + 32;                     // 32 resolved bits (compacted)
    int*      spre   = (int*)(sR + 32);             // 33 valid prefix
    int*      sSp    = spre + 33;                   // 33 starter prefix
    int*      s_wtot = sSp + 33;                    // 32 warp totals
    __shared__ int s_nres, s_nv, s_ng;

    const int b   = blockIdx.x;
    const int tid = threadIdx.x;
    const int w   = tid >> 5;
    const int l   = tid & 31;

    // prefetch mask + coords (latencies overlap)
    const int    v = (mask[(size_t)b * AA + tid] != 0);
    const float2 c = ((const float2*)coords)[(size_t)b * AA + tid];
    {
        unsigned m = __ballot_sync(0xffffffffu, v);
        if (l == 0) svw[w] = m;
    }
    if (tid == 0) s_nres = 0;
    __syncthreads();
    if (tid < 32) {
        int cc = __popc(svw[tid]);
        int x = cc;
#pragma unroll
        for (int o = 1; o < 32; o <<= 1) {
            int y = __shfl_up_sync(0xffffffffu, x, o);
            if (tid >= o) x += y;
        }
        spre[tid] = x - cc;
        if (tid == 31) s_nv = x;
        sS[tid] = 0;
    }
    __syncthreads();
    const int nv = s_nv;
    const int nw = (nv + 31) >> 5;

    if (tid < 32) {   // resolved-init: nonexistent compacted slots are resolved
        int rem = nv - (tid << 5);
        unsigned occ = rem >= 32 ? 0xffffffffu : (rem > 0 ? ((1u << rem) - 1) : 0u);
        sR[tid] = ~occ;
    }
    // scatter valid coords to compacted slots
    if (v) {
        int cp = spre[w] + __popc(svw[w] & ((1u << l) - 1));
        scc[cp] = c;
    }
    __syncthreads();

    // ---- build padded adjacency IN SMEM: 4 rows/warp, word-inner ballots ---
    {
        const u64* scc64 = (const u64*)scc;
        for (int r0 = (w << 2); r0 < nv; r0 += 128) {
            bool h[4];
            u64  ci64[4];
#pragma unroll
            for (int r = 0; r < 4; r++) {
                h[r]    = (r0 + r) < nv;
                ci64[r] = scc64[h[r] ? (r0 + r) : 0];
            }
            for (int k = 0; k < nw; k++) {
                // -cj via sign flip: a + (-b) == a - b exactly (IEEE)
                const u64 ncj = scc64[(k << 5) + l] ^ 0x8000000080000000ULL;
                unsigned m[4];
#pragma unroll
                for (int r = 0; r < 4; r++) {
                    u64 dp, sq;
                    asm("add.rn.f32x2 %0, %1, %2;" : "=l"(dp) : "l"(ci64[r]), "l"(ncj));
                    asm("mul.rn.f32x2 %0, %1, %2;" : "=l"(sq) : "l"(dp), "l"(dp));
                    float lo = __uint_as_float((unsigned)sq);
                    float hi = __uint_as_float((unsigned)(sq >> 32));
                    m[r] = __ballot_sync(0xffffffffu, (lo + hi) < THR2);
                }
                if (l == 0) {
#pragma unroll
                    for (int r = 0; r < 4; r++)
                        if (h[r]) adj[(r0 + r) * 33 + k] = m[r];
                }
            }
        }
    }
    __syncthreads();

    // ---- wavefront: thread tid = compacted agent tid (if < nv) ----
    const bool active = (tid < nv);
    const unsigned ebits = (1u << l) - 1;
    unsigned wm = 0;                       // words with earlier neighbors
    if (active) {
        for (int k = 0; k <= w; k++) {
            unsigned a = adj[tid * 33 + k];
            if (k == w) a &= ebits;
            if (a) wm |= 1u << k;
        }
    }
    bool resolved = !active;
    while (true) {
        bool decR = false, decS = false;
        if (!resolved) {
            bool blocked = false, pend = false;
            unsigned t = wm;
            while (t) {
                int k = __ffs(t) - 1;
                t &= t - 1u;
                unsigned a = adj[tid * 33 + k];
                if (k == w) a &= ebits;
                if (a & sS[k]) { blocked = true; break; }
                if (a & ~sR[k]) pend = true;
            }
            if (blocked)      decR = true;
            else if (!pend) { decS = true; decR = true; }
        }
        __syncthreads();   // snapshot reads complete
        unsigned smw = __ballot_sync(0xffffffffu, decS);
        unsigned rmw = __ballot_sync(0xffffffffu, decR);
        if (l == 0 && smw) sS[w] |= smw;
        if (l == 0 && rmw) { sR[w] |= rmw; atomicAdd(&s_nres, __popc(rmw)); }
        if (decR) resolved = true;
        __syncthreads();   // writes visible
        if (s_nres >= nv) break;
    }

    // starter prefix (rank -> group id)
    if (tid < 32) {
        int cc = __popc(sS[tid]);
        int x = cc;
#pragma unroll
        for (int o = 1; o < 32; o <<= 1) {
            int y = __shfl_up_sync(0xffffffffu, x, o);
            if (tid >= o) x += y;
        }
        sSp[tid] = x - cc;
        if (tid == 31) s_ng = x;
    }
    __syncthreads();

    // asg for ORIGINAL agents: rank of first starter in (compacted row & S)
    int asg = -1;
    if (v) {
        int cp = spre[w] + __popc(svw[w] & ebits);
        int cw = cp >> 5;
        for (int k = 0; k <= cw; k++) {
            unsigned m2 = adj[cp * 33 + k] & sS[k];
            if (m2) {
                int bit = __ffs(m2) - 1;
                asg = sSp[k] + __popc(sS[k] & ((1u << bit) - 1));
                break;
            }
        }
    }
    const int ng = s_ng;

    // ---- member masks via atomicOr into transposed table in dead adj smem --
    __syncthreads();                 // all adj reads done; reuse region
    uint32_t* sMembT = (uint32_t*)sraw;   // [32][1024]: sMembT[w*1024+g]
#pragma unroll
    for (int k = 0; k < 32; k++) sMembT[k * 1024 + tid] = 0;   // conflict-free
    __syncthreads();
    if (v) atomicOr(&sMembT[w * 1024 + asg], 1u << l);         // spread addrs
    __syncthreads();

    // counts: thread tid = group tid (zero for non-groups); conflict-free
    {
        int cnt = 0;
#pragma unroll
        for (int k = 0; k < 32; k++) cnt += __popc(sMembT[k * 1024 + tid]);
        s_cnt[tid] = cnt;
    }
    __syncthreads();

    // ---- exclusive prefix of counts -> s_goff ----
    {
        int val = s_cnt[tid];
        int x = val;
#pragma unroll
        for (int o = 1; o < 32; o <<= 1) {
            int y = __shfl_up_sync(0xffffffffu, x, o);
            if (l >= o) x += y;
        }
        if (l == 31) s_wtot[w] = x;
        __syncthreads();
        if (tid < 32) {
            int cc = s_wtot[tid];
            int y = cc;
#pragma unroll
            for (int o = 1; o < 32; o <<= 1) {
                int z = __shfl_up_sync(0xffffffffu, y, o);
                if (tid >= o) y += z;
            }
            s_wtot[tid] = y - cc;    // exclusive warp offsets
        }
        __syncthreads();
        s_goff[tid] = x - val + s_wtot[w];
    }
    __syncthreads();

    // ---- counting-sorted member list (ascending agent order per group) ----
    if (v) {
        int rank = __popc(sMembT[w * 1024 + asg] & ebits);
        for (int ww = 0; ww < w; ww++) rank += __popc(sMembT[ww * 1024 + asg]);
        g_memlist[b * AA + s_goff[asg] + rank] = tid;
    }

    // emit
    g_cnt[(size_t)b * AA + tid]  = s_cnt[tid];
    g_goff[(size_t)b * AA + tid] = s_goff[tid];
    if (out_a2g)  out_a2g[(size_t)b * AA + tid]  = (float)asg;
    if (out_mask) out_mask[(size_t)b * AA + tid] = (tid < ng) ? 1.0f : 0.0f;
    if (tid == 0) g_ng[b] = ng;
}

// ---------------------------------------------------------------------------
// Kernel 2: fused fill + sparse MLP. [R12/R13 winner — unchanged]
// ---------------------------------------------------------------------------
__global__ __launch_bounds__(512, 1)
void mlp_fill_kernel(const float* __restrict__ emb,
                     const float* __restrict__ W1, const float* __restrict__ b1,
                     const float* __restrict__ W2, const float* __restrict__ b2,
                     float* __restrict__ out)
{
    extern __shared__ float sm[];
    float* sW1T = sm;                  // 16384 floats (4096 float4 slots)
    float* sW2T = sm + 16384;          // 16384
    float* sx   = sm + 32768;          // TMR*DD = 8192
    float* gb1s = sm + 40960;          // 128
    int*   srid = (int*)(sm + 41088);  // 64
    int*   scnt = (int*)(sm + 41152);  // 64

    const int tid  = threadIdx.x;
    const int win  = blockIdx.x;
    const int bb   = win >> 4;              // 16 windows per batch
    const int k0   = (win & 15) * TMR;
    const int ng   = g_ng[bb];
    int live = ng - k0;
    if (live > TMR) live = TMR;
    const bool do_mma = (live > 0);
    const int base = win * TMR;             // == bb*AA + k0

    if (tid < DD) gb1s[tid] = gelu_exact(b1[tid]);
    if (tid < TMR) {
        scnt[tid] = g_cnt[base + tid];
        int rc = tid;
        if (rc > live - 1) rc = live - 1;
        if (rc < 0) rc = 0;
        srid[tid] = base + rc;
    }

    // stage transposed + swizzled weights: slot(c,g) = c*32 + (g ^ ((c>>2)&7))
    // thread mapping c = 4*(i%32) + ((i>>5)&3): conflict-free STS.128.
    if (do_mma) {
        float4* w1t = (float4*)sW1T;
        float4* w2t = (float4*)sW2T;
#pragma unroll
        for (int it = 0; it < 8; it++) {
            int i = tid + it * 512;
            int c = ((i & 31) << 2) | ((i >> 5) & 3);
            int g = i >> 7;
            int slot = c * 32 + (g ^ ((c >> 2) & 7));
            float4 v1, v2;
            v1.x = W1[(4 * g + 0) * DD + c];
            v1.y = W1[(4 * g + 1) * DD + c];
            v1.z = W1[(4 * g + 2) * DD + c];
            v1.w = W1[(4 * g + 3) * DD + c];
            v2.x = W2[(4 * g + 0) * DD + c];
            v2.y = W2[(4 * g + 1) * DD + c];
            v2.z = W2[(4 * g + 2) * DD + c];
            v2.w = W2[(4 * g + 3) * DD + c];
            w1t[slot] = v1;
            w2t[slot] = v2;
        }
    }
    __syncthreads();

    // FILL: constant row for empty groups in this block's window
    if (tid < DD) {
        float a0 = b2[tid], a1 = 0.f, a2 = 0.f, a3 = 0.f;
#pragma unroll 4
        for (int k = 0; k < DD; k += 4) {
            a0 = fmaf(gb1s[k + 0], W2[(k + 0) * DD + tid], a0);
            a1 = fmaf(gb1s[k + 1], W2[(k + 1) * DD + tid], a1);
            a2 = fmaf(gb1s[k + 2], W2[(k + 2) * DD + tid], a2);
            a3 = fmaf(gb1s[k + 3], W2[(k + 3) * DD + tid], a3);
        }
        float cf = (a0 + a1) + (a2 + a3);
        for (int r = 0; r < TMR; r++)
            if (scnt[r] == 0) out[(size_t)(base + r) * DD + tid] = cf;
    }
    if (!do_mma) return;

    const int wp   = tid >> 5;
    const int lane = tid & 31;
    const int r0   = wp * 4;        // 4 rows per warp (16 warps * 4 = 64)
    const int c0   = lane * 4;      // 4 cols per lane
    const int swl  = lane & 7;

    // stage x rows r0..r0+3: mean over contiguous member list.
    int gr4[4], cnt4[4], off4[4];
#pragma unroll
    for (int rr = 0; rr < 4; rr++) {
        gr4[rr]  = srid[r0 + rr];
        cnt4[rr] = scnt[gr4[rr] - base];
        off4[rr] = g_goff[gr4[rr]];        // 4 independent LDGs (overlap)
    }
    const float* ebase = emb + (size_t)bb * AA * DD;
    const int*   mlb   = g_memlist + (size_t)bb * AA;
#pragma unroll 1
    for (int rr = 0; rr < 4; rr++) {
        const int cnt = cnt4[rr];
        const int* ml = mlb + off4[rr];
        float4 a4 = make_float4(0.f, 0.f, 0.f, 0.f);
        int j = 0;
        for (; j + 4 <= cnt; j += 4) {
            int i0 = ml[j], i1 = ml[j + 1], i2 = ml[j + 2], i3 = ml[j + 3];
            float4 v0 = *((const float4*)(ebase + (size_t)i0 * DD) + lane);
            float4 v1 = *((const float4*)(ebase + (size_t)i1 * DD) + lane);
            float4 v2 = *((const float4*)(ebase + (size_t)i2 * DD) + lane);
            float4 v3 = *((const float4*)(ebase + (size_t)i3 * DD) + lane);
            a4.x += (v0.x + v1.x) + (v2.x + v3.x);
            a4.y += (v0.y + v1.y) + (v2.y + v3.y);
            a4.z += (v0.z + v1.z) + (v2.z + v3.z);
            a4.w += (v0.w + v1.w) + (v2.w + v3.w);
        }
        int rem = cnt - j;
        if (rem > 0) {
            // overreads hit g_memlist pad / other entries: values always in
            // [0, AA), so the row loads are safe; contributions gated.
            int i0 = ml[j], i1 = ml[j + 1], i2 = ml[j + 2];
            float f1 = rem > 1 ? 1.f : 0.f;
            float f2 = rem > 2 ? 1.f : 0.f;
            float4 v0 = *((const float4*)(ebase + (size_t)i0 * DD) + lane);
            float4 v1 = *((const float4*)(ebase + (size_t)i1 * DD) + lane);
            float4 v2 = *((const float4*)(ebase + (size_t)i2 * DD) + lane);
            a4.x += v0.x + f1 * v1.x + f2 * v2.x;
            a4.y += v0.y + f1 * v1.y + f2 * v2.y;
            a4.z += v0.z + f1 * v1.z + f2 * v2.z;
            a4.w += v0.w + f1 * v1.w + f2 * v2.w;
        }
        float inv = 1.0f / (float)(cnt > 1 ? cnt : 1);
        a4.x *= inv; a4.y *= inv; a4.z *= inv; a4.w *= inv;
        *(float4*)&sx[(r0 + rr) * DD + c0] = a4;
    }
    __syncwarp();   // warp owns its rows; x within-warp visible

    u64 acc[4][4];

    // ================= layer 1 =================
#pragma unroll
    for (int r = 0; r < 4; r++)
#pragma unroll
        for (int cc = 0; cc < 4; cc++) acc[r][cc] = 0ull;

    {
        const ulonglong2* wp4 = (const ulonglong2*)sW1T;
#pragma unroll 4
        for (int g = 0; g < 32; g++) {
            const int gs = g ^ swl;
            ulonglong2 wv0 = wp4[(c0 + 0) * 32 + gs];
            ulonglong2 wv1 = wp4[(c0 + 1) * 32 + gs];
            ulonglong2 wv2 = wp4[(c0 + 2) * 32 + gs];
            ulonglong2 wv3 = wp4[(c0 + 3) * 32 + gs];
#pragma unroll
            for (int r = 0; r < 4; r++) {
                ulonglong2 xv = *(const ulonglong2*)(sx + (r0 + r) * DD + 4 * g);
                asm("fma.rn.f32x2 %0, %1, %2, %0;" : "+l"(acc[r][0]) : "l"(xv.x), "l"(wv0.x));
                asm("fma.rn.f32x2 %0, %1, %2, %0;" : "+l"(acc[r][1]) : "l"(xv.x), "l"(wv1.x));
                asm("fma.rn.f32x2 %0, %1, %2, %0;" : "+l"(acc[r][2]) : "l"(xv.x), "l"(wv2.x));
                asm("fma.rn.f32x2 %0, %1, %2, %0;" : "+l"(acc[r][3]) : "l"(xv.x), "l"(wv3.x));
                asm("fma.rn.f32x2 %0, %1, %2, %0;" : "+l"(acc[r][0]) : "l"(xv.y), "l"(wv0.y));
                asm("fma.rn.f32x2 %0, %1, %2, %0;" : "+l"(acc[r][1]) : "l"(xv.y), "l"(wv1.y));
                asm("fma.rn.f32x2 %0, %1, %2, %0;" : "+l"(acc[r][2]) : "l"(xv.y), "l"(wv2.y));
                asm("fma.rn.f32x2 %0, %1, %2, %0;" : "+l"(acc[r][3]) : "l"(xv.y), "l"(wv3.y));
            }
        }
    }
    // epilogue 1: h = gelu(lo+hi + b1); warp owns its rows -> no barrier
    {
        float4 bv = *(const float4*)&b1[c0];
#pragma unroll
        for (int r = 0; r < 4; r++) {
            float4 h;
            h.x = gelu_exact(__uint_as_float((unsigned)acc[r][0]) + __uint_as_float((unsigned)(acc[r][0] >> 32)) + bv.x);
            h.y = gelu_exact(__uint_as_float((unsigned)acc[r][1]) + __uint_as_float((unsigned)(acc[r][1] >> 32)) + bv.y);
            h.z = gelu_exact(__uint_as_float((unsigned)acc[r][2]) + __uint_as_float((unsigned)(acc[r][2] >> 32)) + bv.z);
            h.w = gelu_exact(__uint_as_float((unsigned)acc[r][3]) + __uint_as_float((unsigned)(acc[r][3] >> 32)) + bv.w);
            *(float4*)&sx[(r0 + r) * DD + c0] = h;
        }
    }
    __syncwarp();

    // ================= layer 2 =================
#pragma unroll
    for (int r = 0; r < 4; r++)
#pragma unroll
        for (int cc = 0; cc < 4; cc++) acc[r][cc] = 0ull;

    {
        const ulonglong2* wp4 = (const ulonglong2*)sW2T;
#pragma unroll 4
        for (int g = 0; g < 32; g++) {
            const int gs = g ^ swl;
            ulonglong2 wv0 = wp4[(c0 + 0) * 32 + gs];
            ulonglong2 wv1 = wp4[(c0 + 1) * 32 + gs];
            ulonglong2 wv2 = wp4[(c0 + 2) * 32 + gs];
            ulonglong2 wv3 = wp4[(c0 + 3) * 32 + gs];
#pragma unroll
            for (int r = 0; r < 4; r++) {
                ulonglong2 xv = *(const ulonglong2*)(sx + (r0 + r) * DD + 4 * g);
                asm("fma.rn.f32x2 %0, %1, %2, %0;" : "+l"(acc[r][0]) : "l"(xv.x), "l"(wv0.x));
                asm("fma.rn.f32x2 %0, %1, %2, %0;" : "+l"(acc[r][1]) : "l"(xv.x), "l"(wv1.x));
                asm("fma.rn.f32x2 %0, %1, %2, %0;" : "+l"(acc[r][2]) : "l"(xv.x), "l"(wv2.x));
                asm("fma.rn.f32x2 %0, %1, %2, %0;" : "+l"(acc[r][3]) : "l"(xv.x), "l"(wv3.x));
                asm("fma.rn.f32x2 %0, %1, %2, %0;" : "+l"(acc[r][0]) : "l"(xv.y), "l"(wv0.y));
                asm("fma.rn.f32x2 %0, %1, %2, %0;" : "+l"(acc[r][1]) : "l"(xv.y), "l"(wv1.y));
                asm("fma.rn.f32x2 %0, %1, %2, %0;" : "+l"(acc[r][2]) : "l"(xv.y), "l"(wv2.y));
                asm("fma.rn.f32x2 %0, %1, %2, %0;" : "+l"(acc[r][3]) : "l"(xv.y), "l"(wv3.y));
            }
        }
    }
    // epilogue 2: out = lo+hi + b2, store live rows
    {
        float4 bv = *(const float4*)&b2[c0];
#pragma unroll
        for (int r = 0; r < 4; r++) {
            if (r0 + r < live) {
                int gr = srid[r0 + r];
                float4 ov;
                ov.x = __uint_as_float((unsigned)acc[r][0]) + __uint_as_float((unsigned)(acc[r][0] >> 32)) + bv.x;
                ov.y = __uint_as_float((unsigned)acc[r][1]) + __uint_as_float((unsigned)(acc[r][1] >> 32)) + bv.y;
                ov.z = __uint_as_float((unsigned)acc[r][2]) + __uint_as_float((unsigned)(acc[r][2] >> 32)) + bv.z;
                ov.w = __uint_as_float((unsigned)acc[r][3]) + __uint_as_float((unsigned)(acc[r][3] >> 32)) + bv.w;
                *(float4*)&out[(size_t)gr * DD + c0] = ov;
            }
        }
    }
}

// ---------------------------------------------------------------------------
extern "C" void kernel_launch(void* const* d_in, const int* in_sizes, int n_in,
                              void* d_out, int out_size)
{
    const float* emb    = (const float*)d_in[0];
    const float* coords = (const float*)d_in[1];
    const int*   mask   = (const int*)d_in[2];
    const float* W1     = (const float*)d_in[3];
    const float* b1     = (const float*)d_in[4];
    const float* W2     = (const float*)d_in[5];
    const float* b2     = (const float*)d_in[6];

    float* out = (float*)d_out;
    const int tok_elems = BB * AA * DD;
    float* out_mask = (out_size >= tok_elems + BB * AA)     ? out + tok_elems           : nullptr;
    float* out_a2g  = (out_size >= tok_elems + 2 * BB * AA) ? out + tok_elems + BB * AA : nullptr;

    const int smem_scan = AA * 33 * 4 + AA * 8 + 2 * AA * 4
                        + 3 * 32 * 4 + 2 * 33 * 4 + 32 * 4;                    // 152,328
    const int smem_mlp  = (16384 + 16384 + TMR * DD + DD) * 4 + 2 * TMR * 4;   // 164,864

    cudaFuncSetAttribute(scan_kernel,
                         cudaFuncAttributeMaxDynamicSharedMemorySize, smem_scan);
    cudaFuncSetAttribute(mlp_fill_kernel,
                         cudaFuncAttributeMaxDynamicSharedMemorySize, smem_mlp);

    scan_kernel<<<BB, 1024, smem_scan>>>(coords, mask, out_mask, out_a2g);
    mlp_fill_kernel<<<(BB * AA) / TMR, 512, smem_mlp>>>(emb, W1, b1, W2, b2, out);
}

// round 15
// speedup vs baseline: 1.2009x; 1.2009x over previous
#include <cuda_runtime.h>
#include <cstdint>

#define BB 32
#define AA 1024
#define DD 128
#define THR2 0.0025f
#define TMR 64   // MLP rows per block

typedef unsigned long long u64;

// Scratch (allocation-free rule: __device__ globals)
__device__ int      g_cnt[BB * AA];          // per-(batch,group) member counts
__device__ uint32_t g_adj[BB * AA * 32];     // COMPACTED proximity bitmatrix
__device__ int      g_goff[BB * AA];         // per-(batch,group) member-list offset
__device__ int      g_memlist[BB * AA + 8];  // agents counting-sorted by (batch,group); +8 pad
__device__ int      g_ng[BB];                // groups per batch
__device__ float    g_cfill[DD];             // constant row gelu(b1)@W2 + b2

__device__ __forceinline__ float gelu_exact(float x) {
    return 0.5f * x * (1.0f + erff(x * 0.70710678118654752f));
}

// ---------------------------------------------------------------------------
// Kernel 1: COMPACTED adjacency (valid x valid only).  [R13-measured 10.2us]
// grid (8, BB): block (x,b) computes compacted rows [128x, 128x+128).
// ---------------------------------------------------------------------------
__global__ __launch_bounds__(1024, 1)
void adjc_kernel(const float* __restrict__ coords, const int* __restrict__ mask)
{
    __shared__ float2   scc[AA];    // compacted coords
    __shared__ uint32_t svw[32];    // validity words
    __shared__ int      spre[33];   // exclusive prefix of valid counts
    __shared__ int      s_nv;

    const int b   = blockIdx.y;
    const int tid = threadIdx.x;
    const int w   = tid >> 5;
    const int l   = tid & 31;

    // prefetch both global reads up front (latencies overlap)
    const int    v = (mask[(size_t)b * AA + tid] != 0);
    const float2 c = ((const float2*)coords)[(size_t)b * AA + tid];
    {
        unsigned m = __ballot_sync(0xffffffffu, v);
        if (l == 0) svw[w] = m;
    }
    __syncthreads();
    if (tid < 32) {
        int cc = __popc(svw[tid]);
        int x = cc;
#pragma unroll
        for (int o = 1; o < 32; o <<= 1) {
            int y = __shfl_up_sync(0xffffffffu, x, o);
            if (tid >= o) x += y;
        }
        spre[tid] = x - cc;
        if (tid == 31) s_nv = x;
    }
    __syncthreads();
    const int nv = s_nv;

    // scatter valid coords to compacted slots (coords already in regs)
    if (v) {
        int cp = spre[w] + __popc(svw[w] & ((1u << l) - 1));
        scc[cp] = c;
    }
    __syncthreads();

    const int row0 = blockIdx.x * 128;
    if (row0 >= nv) return;
    const int nw = (nv + 31) >> 5;

    const u64* scc64 = (const u64*)scc;
    const int r0 = row0 + (w << 2);   // 4 rows per warp
    bool h[4];
    u64  ci64[4];
#pragma unroll
    for (int r = 0; r < 4; r++) {
        h[r]    = (r0 + r) < nv;
        ci64[r] = scc64[h[r] ? (r0 + r) : 0];
    }
    uint32_t* dst = g_adj + ((size_t)(b * AA) + r0) * 32;

    for (int word = 0; word < nw; word++) {
        // -cj via sign-bit flip: a + (-b) == a - b exactly (IEEE)
        const u64 ncj = scc64[(word << 5) + l] ^ 0x8000000080000000ULL;
        unsigned m[4];
#pragma unroll
        for (int r = 0; r < 4; r++) {
            u64 dp, sq;
            asm("add.rn.f32x2 %0, %1, %2;" : "=l"(dp) : "l"(ci64[r]), "l"(ncj));
            asm("mul.rn.f32x2 %0, %1, %2;" : "=l"(sq) : "l"(dp), "l"(dp));
            float lo = __uint_as_float((unsigned)sq);
            float hi = __uint_as_float((unsigned)(sq >> 32));
            m[r] = __ballot_sync(0xffffffffu, (lo + hi) < THR2);
        }
        if (l == 0) {
#pragma unroll
            for (int r = 0; r < 4; r++)
                if (h[r]) dst[(size_t)r * 32 + word] = m[r];
        }
    }
}

// ---------------------------------------------------------------------------
// Kernel 2: parallel wavefront clustering (32 blocks x 1024 threads).
// [R13-measured core, unchanged] + block 0 additionally computes the constant
// fill row gelu(b1)@W2 + b2 into g_cfill (8-way split-k, deterministic smem
// tree reduce) so the MLP never recomputes it.
// ---------------------------------------------------------------------------
__global__ __launch_bounds__(1024, 1)
void scan_kernel(const int* __restrict__ mask,
                 const float* __restrict__ b1, const float* __restrict__ W2,
                 const float* __restrict__ b2,
                 float* __restrict__ out_mask,   // may be null
                 float* __restrict__ out_a2g)    // may be null
{
    extern __shared__ unsigned char sraw[];
    uint32_t* adj    = (uint32_t*)sraw;             // AA*33 (padded rows)
    int*      s_cnt  = (int*)(adj + AA * 33);       // AA
    int*      s_goff = s_cnt + AA;                  // AA
    uint32_t* svw    = (uint32_t*)(s_goff + AA);    // 32
    uint32_t* sS     = svw + 32;                    // 32 starter bits (compacted)
    uint32_t* sR     = sS + 32;                     // 32 resolved bits (compacted)
    int*      spre   = (int*)(sR + 32);             // 33 valid prefix
    int*      sSp    = spre + 33;                   // 33 starter prefix
    int*      s_wtot = sSp + 33;                    // 32 warp totals
    float*    spart  = (float*)(s_wtot + 32);       // 1024 cfill partials
    __shared__ int s_nres, s_nv, s_ng;

    const int b   = blockIdx.x;
    const int tid = threadIdx.x;
    const int w   = tid >> 5;
    const int l   = tid & 31;

    const int v = (mask[(size_t)b * AA + tid] != 0);
    {
        unsigned m = __ballot_sync(0xffffffffu, v);
        if (l == 0) svw[w] = m;
    }
    if (tid == 0) s_nres = 0;
    __syncthreads();
    if (tid < 32) {
        int c = __popc(svw[tid]);
        int x = c;
#pragma unroll
        for (int o = 1; o < 32; o <<= 1) {
            int y = __shfl_up_sync(0xffffffffu, x, o);
            if (tid >= o) x += y;
        }
        spre[tid] = x - c;
        if (tid == 31) s_nv = x;
        sS[tid] = 0;
    }
    __syncthreads();
    const int nv = s_nv;

    if (tid < 32) {   // resolved-init: nonexistent compacted slots are resolved
        int rem = nv - (tid << 5);
        unsigned occ = rem >= 32 ? 0xffffffffu : (rem > 0 ? ((1u << rem) - 1) : 0u);
        sR[tid] = ~occ;
    }
    // bulk load compacted adjacency rows [0, nv) into PADDED layout (33/row)
    {
        const uint4* src = (const uint4*)(g_adj + (size_t)b * AA * 32);
        const int tot = nv * 8;
        for (int i = tid; i < tot; i += 1024) {
            uint4 v4 = src[i];
            uint32_t* d = adj + (i >> 3) * 33 + ((i & 7) << 2);
            d[0] = v4.x; d[1] = v4.y; d[2] = v4.z; d[3] = v4.w;
        }
    }
    __syncthreads();

    // ---- wavefront: thread tid = compacted agent tid (if < nv) ----
    const bool active = (tid < nv);
    const unsigned ebits = (1u << l) - 1;
    unsigned wm = 0;                       // words with earlier neighbors
    if (active) {
        for (int k = 0; k <= w; k++) {
            unsigned a = adj[tid * 33 + k];
            if (k == w) a &= ebits;
            if (a) wm |= 1u << k;
        }
    }
    bool resolved = !active;
    while (true) {
        bool decR = false, decS = false;
        if (!resolved) {
            bool blocked = false, pend = false;
            unsigned t = wm;
            while (t) {
                int k = __ffs(t) - 1;
                t &= t - 1u;
                unsigned a = adj[tid * 33 + k];
                if (k == w) a &= ebits;
                if (a & sS[k]) { blocked = true; break; }
                if (a & ~sR[k]) pend = true;
            }
            if (blocked)      decR = true;
            else if (!pend) { decS = true; decR = true; }
        }
        __syncthreads();   // snapshot reads complete
        unsigned smw = __ballot_sync(0xffffffffu, decS);
        unsigned rmw = __ballot_sync(0xffffffffu, decR);
        if (l == 0 && smw) sS[w] |= smw;
        if (l == 0 && rmw) { sR[w] |= rmw; atomicAdd(&s_nres, __popc(rmw)); }
        if (decR) resolved = true;
        __syncthreads();   // writes visible
        if (s_nres >= nv) break;
    }

    // starter prefix (rank -> group id)
    if (tid < 32) {
        int c = __popc(sS[tid]);
        int x = c;
#pragma unroll
        for (int o = 1; o < 32; o <<= 1) {
            int y = __shfl_up_sync(0xffffffffu, x, o);
            if (tid >= o) x += y;
        }
        sSp[tid] = x - c;
        if (tid == 31) s_ng = x;
    }
    __syncthreads();

    // asg for ORIGINAL agents: rank of first starter in (compacted row & S)
    int asg = -1;
    if (v) {
        int cp = spre[w] + __popc(svw[w] & ebits);
        int cw = cp >> 5;
        for (int k = 0; k <= cw; k++) {
            unsigned m2 = adj[cp * 33 + k] & sS[k];
            if (m2) {
                int bit = __ffs(m2) - 1;
                asg = sSp[k] + __popc(sS[k] & ((1u << bit) - 1));
                break;
            }
        }
    }
    const int ng = s_ng;

    // ---- member masks via atomicOr into transposed table in dead adj smem --
    __syncthreads();                 // all adj reads done; reuse region
    uint32_t* sMembT = (uint32_t*)sraw;   // [32][1024]: sMembT[w*1024+g]
#pragma unroll
    for (int k = 0; k < 32; k++) sMembT[k * 1024 + tid] = 0;   // conflict-free
    __syncthreads();
    if (v) atomicOr(&sMembT[w * 1024 + asg], 1u << l);         // spread addrs
    __syncthreads();

    // counts: thread tid = group tid (zero for non-groups); conflict-free
    {
        int cnt = 0;
#pragma unroll
        for (int k = 0; k < 32; k++) cnt += __popc(sMembT[k * 1024 + tid]);
        s_cnt[tid] = cnt;
    }
    __syncthreads();

    // ---- exclusive prefix of counts -> s_goff ----
    {
        int val = s_cnt[tid];
        int x = val;
#pragma unroll
        for (int o = 1; o < 32; o <<= 1) {
            int y = __shfl_up_sync(0xffffffffu, x, o);
            if (l >= o) x += y;
        }
        if (l == 31) s_wtot[w] = x;
        __syncthreads();
        if (tid < 32) {
            int cc = s_wtot[tid];
            int y = cc;
#pragma unroll
            for (int o = 1; o < 32; o <<= 1) {
                int z = __shfl_up_sync(0xffffffffu, y, o);
                if (tid >= o) y += z;
            }
            s_wtot[tid] = y - cc;    // exclusive warp offsets
        }
        __syncthreads();
        s_goff[tid] = x - val + s_wtot[w];
    }
    __syncthreads();

    // ---- counting-sorted member list (ascending agent order per group) ----
    if (v) {
        int rank = __popc(sMembT[w * 1024 + asg] & ebits);
        for (int ww = 0; ww < w; ww++) rank += __popc(sMembT[ww * 1024 + asg]);
        g_memlist[b * AA + s_goff[asg] + rank] = tid;
    }

    // emit
    g_cnt[(size_t)b * AA + tid]  = s_cnt[tid];
    g_goff[(size_t)b * AA + tid] = s_goff[tid];
    if (out_a2g)  out_a2g[(size_t)b * AA + tid]  = (float)asg;
    if (out_mask) out_mask[(size_t)b * AA + tid] = (tid < ng) ? 1.0f : 0.0f;
    if (tid == 0) g_ng[b] = ng;

    // ---- block 0: constant fill row gelu(b1)@W2 + b2 -> g_cfill ----
    if (b == 0) {
        const int col = tid & 127;
        const int kq  = tid >> 7;          // 8 k-parts of 16
        float s = 0.f;
        const int kb = kq * 16;
#pragma unroll
        for (int k = 0; k < 16; k++)
            s = fmaf(gelu_exact(b1[kb + k]), W2[(kb + k) * DD + col], s);
        spart[kq * 128 + col] = s;
        __syncthreads();
        if (tid < DD) {
            float acc = b2[tid];
#pragma unroll
            for (int q = 0; q < 8; q++) acc += spart[q * 128 + tid];
            g_cfill[tid] = acc;
        }
    }
}

// ---------------------------------------------------------------------------
// Kernel 3: sparse MLP + fill broadcast. [R13 GEMM core unchanged]
//  - fill-only blocks: coalesced broadcast of g_cfill, immediate return.
//  - live blocks: GATHER FIRST (reads g_cnt/g_goff/g_memlist directly, no
//    smem dependency) so its LDG chains overlap the weight staging across
//    warps; boundary empty rows copied from g_cfill.
// SMEM: W1T 64KB + W2T 64KB + x/h 32KB = 163,840 B dynamic.
// ---------------------------------------------------------------------------
__global__ __launch_bounds__(512, 1)
void mlp_fill_kernel(const float* __restrict__ emb,
                     const float* __restrict__ W1, const float* __restrict__ b1,
                     const float* __restrict__ W2, const float* __restrict__ b2,
                     float* __restrict__ out)
{
    extern __shared__ float sm[];
    float* sW1T = sm;                  // 16384 floats (4096 float4 slots)
    float* sW2T = sm + 16384;          // 16384
    float* sx   = sm + 32768;          // TMR*DD = 8192

    const int tid  = threadIdx.x;
    const int win  = blockIdx.x;
    const int bb   = win >> 4;              // 16 windows per batch
    const int k0   = (win & 15) * TMR;
    const int ng   = g_ng[bb];
    int live = ng - k0;
    if (live > TMR) live = TMR;
    const int base = win * TMR;             // == bb*AA + k0

    if (live <= 0) {
        // fill-only: every row in this window is empty — broadcast g_cfill
        const int col = tid & 127;
        const float cf = g_cfill[col];
        for (int r = tid >> 7; r < TMR; r += 4)
            out[(size_t)(base + r) * DD + col] = cf;
        return;
    }

    const int wp   = tid >> 5;
    const int lane = tid & 31;
    const int r0   = wp * 4;        // 4 rows per warp (16 warps * 4 = 64)
    const int c0   = lane * 4;      // 4 cols per lane
    const int swl  = lane & 7;

    // ---- GATHER FIRST: mean over contiguous member list (globals only) ----
    int gr4[4], cnt4[4], off4[4];
#pragma unroll
    for (int rr = 0; rr < 4; rr++) {
        int rc = r0 + rr;
        if (rc > live - 1) rc = live - 1;
        gr4[rr]  = base + rc;
        cnt4[rr] = g_cnt[gr4[rr]];
        off4[rr] = g_goff[gr4[rr]];        // independent LDGs (overlap)
    }
    const float* ebase = emb + (size_t)bb * AA * DD;
    const int*   mlb   = g_memlist + (size_t)bb * AA;
#pragma unroll 1
    for (int rr = 0; rr < 4; rr++) {
        const int cnt = cnt4[rr];
        const int* ml = mlb + off4[rr];
        float4 a4 = make_float4(0.f, 0.f, 0.f, 0.f);
        int j = 0;
        for (; j + 4 <= cnt; j += 4) {
            int i0 = ml[j], i1 = ml[j + 1], i2 = ml[j + 2], i3 = ml[j + 3];
            float4 v0 = *((const float4*)(ebase + (size_t)i0 * DD) + lane);
            float4 v1 = *((const float4*)(ebase + (size_t)i1 * DD) + lane);
            float4 v2 = *((const float4*)(ebase + (size_t)i2 * DD) + lane);
            float4 v3 = *((const float4*)(ebase + (size_t)i3 * DD) + lane);
            a4.x += (v0.x + v1.x) + (v2.x + v3.x);
            a4.y += (v0.y + v1.y) + (v2.y + v3.y);
            a4.z += (v0.z + v1.z) + (v2.z + v3.z);
            a4.w += (v0.w + v1.w) + (v2.w + v3.w);
        }
        int rem = cnt - j;
        if (rem > 0) {
            // overreads hit zero-init pad / other entries: values in [0, AA),
            // so the row loads are safe; contributions gated.
            int i0 = ml[j], i1 = ml[j + 1], i2 = ml[j + 2];
            float f1 = rem > 1 ? 1.f : 0.f;
            float f2 = rem > 2 ? 1.f : 0.f;
            float4 v0 = *((const float4*)(ebase + (size_t)i0 * DD) + lane);
            float4 v1 = *((const float4*)(ebase + (size_t)i1 * DD) + lane);
            float4 v2 = *((const float4*)(ebase + (size_t)i2 * DD) + lane);
            a4.x += v0.x + f1 * v1.x + f2 * v2.x;
            a4.y += v0.y + f1 * v1.y + f2 * v2.y;
            a4.z += v0.z + f1 * v1.z + f2 * v2.z;
            a4.w += v0.w + f1 * v1.w + f2 * v2.w;
        }
        float inv = 1.0f / (float)(cnt > 1 ? cnt : 1);
        a4.x *= inv; a4.y *= inv; a4.z *= inv; a4.w *= inv;
        *(float4*)&sx[(r0 + rr) * DD + c0] = a4;
    }

    // ---- weight staging: slot(c,g) = c*32 + (g ^ ((c>>2)&7)), conflict-free
    {
        float4* w1t = (float4*)sW1T;
        float4* w2t = (float4*)sW2T;
#pragma unroll
        for (int it = 0; it < 8; it++) {
            int i = tid + it * 512;
            int c = ((i & 31) << 2) | ((i >> 5) & 3);
            int g = i >> 7;
            int slot = c * 32 + (g ^ ((c >> 2) & 7));
            float4 v1, v2;
            v1.x = W1[(4 * g + 0) * DD + c];
            v1.y = W1[(4 * g + 1) * DD + c];
            v1.z = W1[(4 * g + 2) * DD + c];
            v1.w = W1[(4 * g + 3) * DD + c];
            v2.x = W2[(4 * g + 0) * DD + c];
            v2.y = W2[(4 * g + 1) * DD + c];
            v2.z = W2[(4 * g + 2) * DD + c];
            v2.w = W2[(4 * g + 3) * DD + c];
            w1t[slot] = v1;
            w2t[slot] = v2;
        }
    }
    __syncthreads();

    // boundary fill: rows [live, TMR) of this window are empty
    if (live < TMR && tid < DD) {
        float cf = g_cfill[tid];
        for (int r = live; r < TMR; r++)
            out[(size_t)(base + r) * DD + tid] = cf;
    }

    u64 acc[4][4];

    // ================= layer 1 =================
#pragma unroll
    for (int r = 0; r < 4; r++)
#pragma unroll
        for (int cc = 0; cc < 4; cc++) acc[r][cc] = 0ull;

    {
        const ulonglong2* wp4 = (const ulonglong2*)sW1T;
#pragma unroll 4
        for (int g = 0; g < 32; g++) {
            const int gs = g ^ swl;
            ulonglong2 wv0 = wp4[(c0 + 0) * 32 + gs];
            ulonglong2 wv1 = wp4[(c0 + 1) * 32 + gs];
            ulonglong2 wv2 = wp4[(c0 + 2) * 32 + gs];
            ulonglong2 wv3 = wp4[(c0 + 3) * 32 + gs];
#pragma unroll
            for (int r = 0; r < 4; r++) {
                ulonglong2 xv = *(const ulonglong2*)(sx + (r0 + r) * DD + 4 * g);
                asm("fma.rn.f32x2 %0, %1, %2, %0;" : "+l"(acc[r][0]) : "l"(xv.x), "l"(wv0.x));
                asm("fma.rn.f32x2 %0, %1, %2, %0;" : "+l"(acc[r][1]) : "l"(xv.x), "l"(wv1.x));
                asm("fma.rn.f32x2 %0, %1, %2, %0;" : "+l"(acc[r][2]) : "l"(xv.x), "l"(wv2.x));
                asm("fma.rn.f32x2 %0, %1, %2, %0;" : "+l"(acc[r][3]) : "l"(xv.x), "l"(wv3.x));
                asm("fma.rn.f32x2 %0, %1, %2, %0;" : "+l"(acc[r][0]) : "l"(xv.y), "l"(wv0.y));
                asm("fma.rn.f32x2 %0, %1, %2, %0;" : "+l"(acc[r][1]) : "l"(xv.y), "l"(wv1.y));
                asm("fma.rn.f32x2 %0, %1, %2, %0;" : "+l"(acc[r][2]) : "l"(xv.y), "l"(wv2.y));
                asm("fma.rn.f32x2 %0, %1, %2, %0;" : "+l"(acc[r][3]) : "l"(xv.y), "l"(wv3.y));
            }
        }
    }
    // epilogue 1: h = gelu(lo+hi + b1); warp owns its rows -> no barrier
    {
        float4 bv = *(const float4*)&b1[c0];
#pragma unroll
        for (int r = 0; r < 4; r++) {
            float4 h;
            h.x = gelu_exact(__uint_as_float((unsigned)acc[r][0]) + __uint_as_float((unsigned)(acc[r][0] >> 32)) + bv.x);
            h.y = gelu_exact(__uint_as_float((unsigned)acc[r][1]) + __uint_as_float((unsigned)(acc[r][1] >> 32)) + bv.y);
            h.z = gelu_exact(__uint_as_float((unsigned)acc[r][2]) + __uint_as_float((unsigned)(acc[r][2] >> 32)) + bv.z);
            h.w = gelu_exact(__uint_as_float((unsigned)acc[r][3]) + __uint_as_float((unsigned)(acc[r][3] >> 32)) + bv.w);
            *(float4*)&sx[(r0 + r) * DD + c0] = h;
        }
    }
    __syncwarp();

    // ================= layer 2 =================
#pragma unroll
    for (int r = 0; r < 4; r++)
#pragma unroll
        for (int cc = 0; cc < 4; cc++) acc[r][cc] = 0ull;

    {
        const ulonglong2* wp4 = (const ulonglong2*)sW2T;
#pragma unroll 4
        for (int g = 0; g < 32; g++) {
            const int gs = g ^ swl;
            ulonglong2 wv0 = wp4[(c0 + 0) * 32 + gs];
            ulonglong2 wv1 = wp4[(c0 + 1) * 32 + gs];
            ulonglong2 wv2 = wp4[(c0 + 2) * 32 + gs];
            ulonglong2 wv3 = wp4[(c0 + 3) * 32 + gs];
#pragma unroll
            for (int r = 0; r < 4; r++) {
                ulonglong2 xv = *(const ulonglong2*)(sx + (r0 + r) * DD + 4 * g);
                asm("fma.rn.f32x2 %0, %1, %2, %0;" : "+l"(acc[r][0]) : "l"(xv.x), "l"(wv0.x));
                asm("fma.rn.f32x2 %0, %1, %2, %0;" : "+l"(acc[r][1]) : "l"(xv.x), "l"(wv1.x));
                asm("fma.rn.f32x2 %0, %1, %2, %0;" : "+l"(acc[r][2]) : "l"(xv.x), "l"(wv2.x));
                asm("fma.rn.f32x2 %0, %1, %2, %0;" : "+l"(acc[r][3]) : "l"(xv.x), "l"(wv3.x));
                asm("fma.rn.f32x2 %0, %1, %2, %0;" : "+l"(acc[r][0]) : "l"(xv.y), "l"(wv0.y));
                asm("fma.rn.f32x2 %0, %1, %2, %0;" : "+l"(acc[r][1]) : "l"(xv.y), "l"(wv1.y));
                asm("fma.rn.f32x2 %0, %1, %2, %0;" : "+l"(acc[r][2]) : "l"(xv.y), "l"(wv2.y));
                asm("fma.rn.f32x2 %0, %1, %2, %0;" : "+l"(acc[r][3]) : "l"(xv.y), "l"(wv3.y));
            }
        }
    }
    // epilogue 2: out = lo+hi + b2, store live rows
    {
        float4 bv = *(const float4*)&b2[c0];
#pragma unroll
        for (int r = 0; r < 4; r++) {
            if (r0 + r < live) {
                float4 ov;
                ov.x = __uint_as_float((unsigned)acc[r][0]) + __uint_as_float((unsigned)(acc[r][0] >> 32)) + bv.x;
                ov.y = __uint_as_float((unsigned)acc[r][1]) + __uint_as_float((unsigned)(acc[r][1] >> 32)) + bv.y;
                ov.z = __uint_as_float((unsigned)acc[r][2]) + __uint_as_float((unsigned)(acc[r][2] >> 32)) + bv.z;
                ov.w = __uint_as_float((unsigned)acc[r][3]) + __uint_as_float((unsigned)(acc[r][3] >> 32)) + bv.w;
                *(float4*)&out[(size_t)gr4[r] * DD + c0] = ov;
            }
        }
    }
}

// ---------------------------------------------------------------------------
extern "C" void kernel_launch(void* const* d_in, const int* in_sizes, int n_in,
                              void* d_out, int out_size)
{
    const float* emb    = (const float*)d_in[0];
    const float* coords = (const float*)d_in[1];
    const int*   mask   = (const int*)d_in[2];
    const float* W1     = (const float*)d_in[3];
    const float* b1     = (const float*)d_in[4];
    const float* W2     = (const float*)d_in[5];
    const float* b2     = (const float*)d_in[6];

    float* out = (float*)d_out;
    const int tok_elems = BB * AA * DD;
    float* out_mask = (out_size >= tok_elems + BB * AA)     ? out + tok_elems           : nullptr;
    float* out_a2g  = (out_size >= tok_elems + 2 * BB * AA) ? out + tok_elems + BB * AA : nullptr;

    const int smem_scan = AA * 33 * 4 + 2 * AA * 4 + 3 * 32 * 4 + 2 * 33 * 4
                        + 32 * 4 + 1024 * 4;                                   // 148,232
    const int smem_mlp  = (16384 + 16384 + TMR * DD) * 4;                      // 163,840

    cudaFuncSetAttribute(scan_kernel,
                         cudaFuncAttributeMaxDynamicSharedMemorySize, smem_scan);
    cudaFuncSetAttribute(mlp_fill_kernel,
                         cudaFuncAttributeMaxDynamicSharedMemorySize, smem_mlp);

    adjc_kernel<<<dim3(8, BB), 1024>>>(coords, mask);
    scan_kernel<<<BB, 1024, smem_scan>>>(mask, b1, W2, b2, out_mask, out_a2g);
    mlp_fill_kernel<<<(BB * AA) / TMR, 512, smem_mlp>>>(emb, W1, b1, W2, b2, out);
}

// round 16
// speedup vs baseline: 1.2063x; 1.0045x over previous
#include <cuda_runtime.h>
#include <cstdint>

#define BB 32
#define AA 1024
#define DD 128
#define THR2 0.0025f
#define TMR 64   // MLP rows per block

typedef unsigned long long u64;

// Scratch (allocation-free rule: __device__ globals)
__device__ int      g_cnt[BB * AA];          // per-(batch,group) member counts
__device__ uint32_t g_adj[BB * AA * 32];     // COMPACTED proximity bitmatrix (lower triangle only)
__device__ int      g_goff[BB * AA];         // per-(batch,group) member-list offset
__device__ int      g_memlist[BB * AA + 8];  // agents counting-sorted by (batch,group); +8 pad
__device__ int      g_ng[BB];                // groups per batch
__device__ float    g_cfill[DD];             // constant row gelu(b1)@W2 + b2

__device__ __forceinline__ float gelu_exact(float x) {
    return 0.5f * x * (1.0f + erff(x * 0.70710678118654752f));
}

// ---------------------------------------------------------------------------
// Kernel 1: COMPACTED adjacency — LOWER TRIANGLE ONLY (all consumers read
// words k <= row>>5 only; the diagonal word is computed in full).
// grid (8, BB): block (x,b) computes compacted rows [128x, 128x+128).
// ---------------------------------------------------------------------------
__global__ __launch_bounds__(1024, 1)
void adjc_kernel(const float* __restrict__ coords, const int* __restrict__ mask)
{
    __shared__ float2   scc[AA];    // compacted coords
    __shared__ uint32_t svw[32];    // validity words
    __shared__ int      spre[33];   // exclusive prefix of valid counts
    __shared__ int      s_nv;

    const int b   = blockIdx.y;
    const int tid = threadIdx.x;
    const int w   = tid >> 5;
    const int l   = tid & 31;

    // prefetch both global reads up front (latencies overlap)
    const int    v = (mask[(size_t)b * AA + tid] != 0);
    const float2 c = ((const float2*)coords)[(size_t)b * AA + tid];
    {
        unsigned m = __ballot_sync(0xffffffffu, v);
        if (l == 0) svw[w] = m;
    }
    __syncthreads();
    if (tid < 32) {
        int cc = __popc(svw[tid]);
        int x = cc;
#pragma unroll
        for (int o = 1; o < 32; o <<= 1) {
            int y = __shfl_up_sync(0xffffffffu, x, o);
            if (tid >= o) x += y;
        }
        spre[tid] = x - cc;
        if (tid == 31) s_nv = x;
    }
    __syncthreads();
    const int nv = s_nv;

    // scatter valid coords to compacted slots (coords already in regs)
    if (v) {
        int cp = spre[w] + __popc(svw[w] & ((1u << l) - 1));
        scc[cp] = c;
    }
    __syncthreads();

    const int row0 = blockIdx.x * 128;
    if (row0 >= nv) return;

    const u64* scc64 = (const u64*)scc;
    const int r0 = row0 + (w << 2);   // 4 rows per warp
    bool h[4];
    u64  ci64[4];
#pragma unroll
    for (int r = 0; r < 4; r++) {
        h[r]    = (r0 + r) < nv;
        ci64[r] = scc64[h[r] ? (r0 + r) : 0];
    }
    uint32_t* dst = g_adj + ((size_t)(b * AA) + r0) * 32;

    // lower triangle: word k needed only for k <= row>>5 (diag word in full)
    int wmax = ((r0 + 3) < nv ? (r0 + 3) : (nv - 1)) >> 5;   // warp-uniform
    for (int word = 0; word <= wmax; word++) {
        // -cj via sign-bit flip: a + (-b) == a - b exactly (IEEE)
        const u64 ncj = scc64[(word << 5) + l] ^ 0x8000000080000000ULL;
        unsigned m[4];
#pragma unroll
        for (int r = 0; r < 4; r++) {
            u64 dp, sq;
            asm("add.rn.f32x2 %0, %1, %2;" : "=l"(dp) : "l"(ci64[r]), "l"(ncj));
            asm("mul.rn.f32x2 %0, %1, %2;" : "=l"(sq) : "l"(dp), "l"(dp));
            float lo = __uint_as_float((unsigned)sq);
            float hi = __uint_as_float((unsigned)(sq >> 32));
            m[r] = __ballot_sync(0xffffffffu, (lo + hi) < THR2);
        }
        if (l == 0) {
#pragma unroll
            for (int r = 0; r < 4; r++)
                if (h[r] && word <= ((r0 + r) >> 5))
                    dst[(size_t)r * 32 + word] = m[r];
        }
    }
}

// ---------------------------------------------------------------------------
// Kernel 2: parallel wavefront clustering (32 blocks x 1024 threads).
// [R15 core] — bulk load now skips quads outside the lower triangle.
// Block 0 additionally computes g_cfill = gelu(b1)@W2 + b2.
// ---------------------------------------------------------------------------
__global__ __launch_bounds__(1024, 1)
void scan_kernel(const int* __restrict__ mask,
                 const float* __restrict__ b1, const float* __restrict__ W2,
                 const float* __restrict__ b2,
                 float* __restrict__ out_mask,   // may be null
                 float* __restrict__ out_a2g)    // may be null
{
    extern __shared__ unsigned char sraw[];
    uint32_t* adj    = (uint32_t*)sraw;             // AA*33 (padded rows)
    int*      s_cnt  = (int*)(adj + AA * 33);       // AA
    int*      s_goff = s_cnt + AA;                  // AA
    uint32_t* svw    = (uint32_t*)(s_goff + AA);    // 32
    uint32_t* sS     = svw + 32;                    // 32 starter bits (compacted)
    uint32_t* sR     = sS + 32;                     // 32 resolved bits (compacted)
    int*      spre   = (int*)(sR + 32);             // 33 valid prefix
    int*      sSp    = spre + 33;                   // 33 starter prefix
    int*      s_wtot = sSp + 33;                    // 32 warp totals
    float*    spart  = (float*)(s_wtot + 32);       // 1024 cfill partials
    __shared__ int s_nres, s_nv, s_ng;

    const int b   = blockIdx.x;
    const int tid = threadIdx.x;
    const int w   = tid >> 5;
    const int l   = tid & 31;

    const int v = (mask[(size_t)b * AA + tid] != 0);
    {
        unsigned m = __ballot_sync(0xffffffffu, v);
        if (l == 0) svw[w] = m;
    }
    if (tid == 0) s_nres = 0;
    __syncthreads();
    if (tid < 32) {
        int c = __popc(svw[tid]);
        int x = c;
#pragma unroll
        for (int o = 1; o < 32; o <<= 1) {
            int y = __shfl_up_sync(0xffffffffu, x, o);
            if (tid >= o) x += y;
        }
        spre[tid] = x - c;
        if (tid == 31) s_nv = x;
        sS[tid] = 0;
    }
    __syncthreads();
    const int nv = s_nv;

    if (tid < 32) {   // resolved-init: nonexistent compacted slots are resolved
        int rem = nv - (tid << 5);
        unsigned occ = rem >= 32 ? 0xffffffffu : (rem > 0 ? ((1u << rem) - 1) : 0u);
        sR[tid] = ~occ;
    }
    // bulk load compacted adjacency rows [0, nv) into PADDED layout (33/row).
    // Only quads inside the lower triangle (quad <= row>>7) are written —
    // upper words are never read by any consumer.
    {
        const uint4* src = (const uint4*)(g_adj + (size_t)b * AA * 32);
        const int tot = nv * 8;
        for (int i = tid; i < tot; i += 1024) {
            if (((i & 7) << 7) <= (i >> 3)) {      // quad*4 <= row>>5
                uint4 v4 = src[i];
                uint32_t* d = adj + (i >> 3) * 33 + ((i & 7) << 2);
                d[0] = v4.x; d[1] = v4.y; d[2] = v4.z; d[3] = v4.w;
            }
        }
    }
    __syncthreads();

    // ---- wavefront: thread tid = compacted agent tid (if < nv) ----
    const bool active = (tid < nv);
    const unsigned ebits = (1u << l) - 1;
    unsigned wm = 0;                       // words with earlier neighbors
    if (active) {
        for (int k = 0; k <= w; k++) {
            unsigned a = adj[tid * 33 + k];
            if (k == w) a &= ebits;
            if (a) wm |= 1u << k;
        }
    }
    bool resolved = !active;
    while (true) {
        bool decR = false, decS = false;
        if (!resolved) {
            bool blocked = false, pend = false;
            unsigned t = wm;
            while (t) {
                int k = __ffs(t) - 1;
                t &= t - 1u;
                unsigned a = adj[tid * 33 + k];
                if (k == w) a &= ebits;
                if (a & sS[k]) { blocked = true; break; }
                if (a & ~sR[k]) pend = true;
            }
            if (blocked)      decR = true;
            else if (!pend) { decS = true; decR = true; }
        }
        __syncthreads();   // snapshot reads complete
        unsigned smw = __ballot_sync(0xffffffffu, decS);
        unsigned rmw = __ballot_sync(0xffffffffu, decR);
        if (l == 0 && smw) sS[w] |= smw;
        if (l == 0 && rmw) { sR[w] |= rmw; atomicAdd(&s_nres, __popc(rmw)); }
        if (decR) resolved = true;
        __syncthreads();   // writes visible
        if (s_nres >= nv) break;
    }

    // starter prefix (rank -> group id)
    if (tid < 32) {
        int c = __popc(sS[tid]);
        int x = c;
#pragma unroll
        for (int o = 1; o < 32; o <<= 1) {
            int y = __shfl_up_sync(0xffffffffu, x, o);
            if (tid >= o) x += y;
        }
        sSp[tid] = x - c;
        if (tid == 31) s_ng = x;
    }
    __syncthreads();

    // asg for ORIGINAL agents: rank of first starter in (compacted row & S)
    int asg = -1;
    if (v) {
        int cp = spre[w] + __popc(svw[w] & ebits);
        int cw = cp >> 5;
        for (int k = 0; k <= cw; k++) {
            unsigned m2 = adj[cp * 33 + k] & sS[k];
            if (m2) {
                int bit = __ffs(m2) - 1;
                asg = sSp[k] + __popc(sS[k] & ((1u << bit) - 1));
                break;
            }
        }
    }
    const int ng = s_ng;

    // ---- member masks via atomicOr into transposed table in dead adj smem --
    __syncthreads();                 // all adj reads done; reuse region
    uint32_t* sMembT = (uint32_t*)sraw;   // [32][1024]: sMembT[w*1024+g]
#pragma unroll
    for (int k = 0; k < 32; k++) sMembT[k * 1024 + tid] = 0;   // conflict-free
    __syncthreads();
    if (v) atomicOr(&sMembT[w * 1024 + asg], 1u << l);         // spread addrs
    __syncthreads();

    // counts: thread tid = group tid (zero for non-groups); conflict-free
    {
        int cnt = 0;
#pragma unroll
        for (int k = 0; k < 32; k++) cnt += __popc(sMembT[k * 1024 + tid]);
        s_cnt[tid] = cnt;
    }
    __syncthreads();

    // ---- exclusive prefix of counts -> s_goff ----
    {
        int val = s_cnt[tid];
        int x = val;
#pragma unroll
        for (int o = 1; o < 32; o <<= 1) {
            int y = __shfl_up_sync(0xffffffffu, x, o);
            if (l >= o) x += y;
        }
        if (l == 31) s_wtot[w] = x;
        __syncthreads();
        if (tid < 32) {
            int cc = s_wtot[tid];
            int y = cc;
#pragma unroll
            for (int o = 1; o < 32; o <<= 1) {
                int z = __shfl_up_sync(0xffffffffu, y, o);
                if (tid >= o) y += z;
            }
            s_wtot[tid] = y - cc;    // exclusive warp offsets
        }
        __syncthreads();
        s_goff[tid] = x - val + s_wtot[w];
    }
    __syncthreads();

    // ---- counting-sorted member list (ascending agent order per group) ----
    if (v) {
        int rank = __popc(sMembT[w * 1024 + asg] & ebits);
        for (int ww = 0; ww < w; ww++) rank += __popc(sMembT[ww * 1024 + asg]);
        g_memlist[b * AA + s_goff[asg] + rank] = tid;
    }

    // emit
    g_cnt[(size_t)b * AA + tid]  = s_cnt[tid];
    g_goff[(size_t)b * AA + tid] = s_goff[tid];
    if (out_a2g)  out_a2g[(size_t)b * AA + tid]  = (float)asg;
    if (out_mask) out_mask[(size_t)b * AA + tid] = (tid < ng) ? 1.0f : 0.0f;
    if (tid == 0) g_ng[b] = ng;

    // ---- block 0: constant fill row gelu(b1)@W2 + b2 -> g_cfill ----
    if (b == 0) {
        const int col = tid & 127;
        const int kq  = tid >> 7;          // 8 k-parts of 16
        float s = 0.f;
        const int kb = kq * 16;
#pragma unroll
        for (int k = 0; k < 16; k++)
            s = fmaf(gelu_exact(b1[kb + k]), W2[(kb + k) * DD + col], s);
        spart[kq * 128 + col] = s;
        __syncthreads();
        if (tid < DD) {
            float acc = b2[tid];
#pragma unroll
            for (int q = 0; q < 8; q++) acc += spart[q * 128 + tid];
            g_cfill[tid] = acc;
        }
    }
}

// ---------------------------------------------------------------------------
// Kernel 3: sparse MLP + fill broadcast. [R15 winner — unchanged]
// ---------------------------------------------------------------------------
__global__ __launch_bounds__(512, 1)
void mlp_fill_kernel(const float* __restrict__ emb,
                     const float* __restrict__ W1, const float* __restrict__ b1,
                     const float* __restrict__ W2, const float* __restrict__ b2,
                     float* __restrict__ out)
{
    extern __shared__ float sm[];
    float* sW1T = sm;                  // 16384 floats (4096 float4 slots)
    float* sW2T = sm + 16384;          // 16384
    float* sx   = sm + 32768;          // TMR*DD = 8192

    const int tid  = threadIdx.x;
    const int win  = blockIdx.x;
    const int bb   = win >> 4;              // 16 windows per batch
    const int k0   = (win & 15) * TMR;
    const int ng   = g_ng[bb];
    int live = ng - k0;
    if (live > TMR) live = TMR;
    const int base = win * TMR;             // == bb*AA + k0

    if (live <= 0) {
        // fill-only: every row in this window is empty — broadcast g_cfill
        const int col = tid & 127;
        const float cf = g_cfill[col];
        for (int r = tid >> 7; r < TMR; r += 4)
            out[(size_t)(base + r) * DD + col] = cf;
        return;
    }

    const int wp   = tid >> 5;
    const int lane = tid & 31;
    const int r0   = wp * 4;        // 4 rows per warp (16 warps * 4 = 64)
    const int c0   = lane * 4;      // 4 cols per lane
    const int swl  = lane & 7;

    // ---- GATHER FIRST: mean over contiguous member list (globals only) ----
    int gr4[4], cnt4[4], off4[4];
#pragma unroll
    for (int rr = 0; rr < 4; rr++) {
        int rc = r0 + rr;
        if (rc > live - 1) rc = live - 1;
        gr4[rr]  = base + rc;
        cnt4[rr] = g_cnt[gr4[rr]];
        off4[rr] = g_goff[gr4[rr]];        // independent LDGs (overlap)
    }
    const float* ebase = emb + (size_t)bb * AA * DD;
    const int*   mlb   = g_memlist + (size_t)bb * AA;
#pragma unroll 1
    for (int rr = 0; rr < 4; rr++) {
        const int cnt = cnt4[rr];
        const int* ml = mlb + off4[rr];
        float4 a4 = make_float4(0.f, 0.f, 0.f, 0.f);
        int j = 0;
        for (; j + 4 <= cnt; j += 4) {
            int i0 = ml[j], i1 = ml[j + 1], i2 = ml[j + 2], i3 = ml[j + 3];
            float4 v0 = *((const float4*)(ebase + (size_t)i0 * DD) + lane);
            float4 v1 = *((const float4*)(ebase + (size_t)i1 * DD) + lane);
            float4 v2 = *((const float4*)(ebase + (size_t)i2 * DD) + lane);
            float4 v3 = *((const float4*)(ebase + (size_t)i3 * DD) + lane);
            a4.x += (v0.x + v1.x) + (v2.x + v3.x);
            a4.y += (v0.y + v1.y) + (v2.y + v3.y);
            a4.z += (v0.z + v1.z) + (v2.z + v3.z);
            a4.w += (v0.w + v1.w) + (v2.w + v3.w);
        }
        int rem = cnt - j;
        if (rem > 0) {
            // overreads hit zero-init pad / other entries: values in [0, AA),
            // so the row loads are safe; contributions gated.
            int i0 = ml[j], i1 = ml[j + 1], i2 = ml[j + 2];
            float f1 = rem > 1 ? 1.f : 0.f;
            float f2 = rem > 2 ? 1.f : 0.f;
            float4 v0 = *((const float4*)(ebase + (size_t)i0 * DD) + lane);
            float4 v1 = *((const float4*)(ebase + (size_t)i1 * DD) + lane);
            float4 v2 = *((const float4*)(ebase + (size_t)i2 * DD) + lane);
            a4.x += v0.x + f1 * v1.x + f2 * v2.x;
            a4.y += v0.y + f1 * v1.y + f2 * v2.y;
            a4.z += v0.z + f1 * v1.z + f2 * v2.z;
            a4.w += v0.w + f1 * v1.w + f2 * v2.w;
        }
        float inv = 1.0f / (float)(cnt > 1 ? cnt : 1);
        a4.x *= inv; a4.y *= inv; a4.z *= inv; a4.w *= inv;
        *(float4*)&sx[(r0 + rr) * DD + c0] = a4;
    }

    // ---- weight staging: slot(c,g) = c*32 + (g ^ ((c>>2)&7)), conflict-free
    {
        float4* w1t = (float4*)sW1T;
        float4* w2t = (float4*)sW2T;
#pragma unroll
        for (int it = 0; it < 8; it++) {
            int i = tid + it * 512;
            int c = ((i & 31) << 2) | ((i >> 5) & 3);
            int g = i >> 7;
            int slot = c * 32 + (g ^ ((c >> 2) & 7));
            float4 v1, v2;
            v1.x = W1[(4 * g + 0) * DD + c];
            v1.y = W1[(4 * g + 1) * DD + c];
            v1.z = W1[(4 * g + 2) * DD + c];
            v1.w = W1[(4 * g + 3) * DD + c];
            v2.x = W2[(4 * g + 0) * DD + c];
            v2.y = W2[(4 * g + 1) * DD + c];
            v2.z = W2[(4 * g + 2) * DD + c];
            v2.w = W2[(4 * g + 3) * DD + c];
            w1t[slot] = v1;
            w2t[slot] = v2;
        }
    }
    __syncthreads();

    // boundary fill: rows [live, TMR) of this window are empty
    if (live < TMR && tid < DD) {
        float cf = g_cfill[tid];
        for (int r = live; r < TMR; r++)
            out[(size_t)(base + r) * DD + tid] = cf;
    }

    u64 acc[4][4];

    // ================= layer 1 =================
#pragma unroll
    for (int r = 0; r < 4; r++)
#pragma unroll
        for (int cc = 0; cc < 4; cc++) acc[r][cc] = 0ull;

    {
        const ulonglong2* wp4 = (const ulonglong2*)sW1T;
#pragma unroll 4
        for (int g = 0; g < 32; g++) {
            const int gs = g ^ swl;
            ulonglong2 wv0 = wp4[(c0 + 0) * 32 + gs];
            ulonglong2 wv1 = wp4[(c0 + 1) * 32 + gs];
            ulonglong2 wv2 = wp4[(c0 + 2) * 32 + gs];
            ulonglong2 wv3 = wp4[(c0 + 3) * 32 + gs];
#pragma unroll
            for (int r = 0; r < 4; r++) {
                ulonglong2 xv = *(const ulonglong2*)(sx + (r0 + r) * DD + 4 * g);
                asm("fma.rn.f32x2 %0, %1, %2, %0;" : "+l"(acc[r][0]) : "l"(xv.x), "l"(wv0.x));
                asm("fma.rn.f32x2 %0, %1, %2, %0;" : "+l"(acc[r][1]) : "l"(xv.x), "l"(wv1.x));
                asm("fma.rn.f32x2 %0, %1, %2, %0;" : "+l"(acc[r][2]) : "l"(xv.x), "l"(wv2.x));
                asm("fma.rn.f32x2 %0, %1, %2, %0;" : "+l"(acc[r][3]) : "l"(xv.x), "l"(wv3.x));
                asm("fma.rn.f32x2 %0, %1, %2, %0;" : "+l"(acc[r][0]) : "l"(xv.y), "l"(wv0.y));
                asm("fma.rn.f32x2 %0, %1, %2, %0;" : "+l"(acc[r][1]) : "l"(xv.y), "l"(wv1.y));
                asm("fma.rn.f32x2 %0, %1, %2, %0;" : "+l"(acc[r][2]) : "l"(xv.y), "l"(wv2.y));
                asm("fma.rn.f32x2 %0, %1, %2, %0;" : "+l"(acc[r][3]) : "l"(xv.y), "l"(wv3.y));
            }
        }
    }
    // epilogue 1: h = gelu(lo+hi + b1); warp owns its rows -> no barrier
    {
        float4 bv = *(const float4*)&b1[c0];
#pragma unroll
        for (int r = 0; r < 4; r++) {
            float4 h;
            h.x = gelu_exact(__uint_as_float((unsigned)acc[r][0]) + __uint_as_float((unsigned)(acc[r][0] >> 32)) + bv.x);
            h.y = gelu_exact(__uint_as_float((unsigned)acc[r][1]) + __uint_as_float((unsigned)(acc[r][1] >> 32)) + bv.y);
            h.z = gelu_exact(__uint_as_float((unsigned)acc[r][2]) + __uint_as_float((unsigned)(acc[r][2] >> 32)) + bv.z);
            h.w = gelu_exact(__uint_as_float((unsigned)acc[r][3]) + __uint_as_float((unsigned)(acc[r][3] >> 32)) + bv.w);
            *(float4*)&sx[(r0 + r) * DD + c0] = h;
        }
    }
    __syncwarp();

    // ================= layer 2 =================
#pragma unroll
    for (int r = 0; r < 4; r++)
#pragma unroll
        for (int cc = 0; cc < 4; cc++) acc[r][cc] = 0ull;

    {
        const ulonglong2* wp4 = (const ulonglong2*)sW2T;
#pragma unroll 4
        for (int g = 0; g < 32; g++) {
            const int gs = g ^ swl;
            ulonglong2 wv0 = wp4[(c0 + 0) * 32 + gs];
            ulonglong2 wv1 = wp4[(c0 + 1) * 32 + gs];
            ulonglong2 wv2 = wp4[(c0 + 2) * 32 + gs];
            ulonglong2 wv3 = wp4[(c0 + 3) * 32 + gs];
#pragma unroll
            for (int r = 0; r < 4; r++) {
                ulonglong2 xv = *(const ulonglong2*)(sx + (r0 + r) * DD + 4 * g);
                asm("fma.rn.f32x2 %0, %1, %2, %0;" : "+l"(acc[r][0]) : "l"(xv.x), "l"(wv0.x));
                asm("fma.rn.f32x2 %0, %1, %2, %0;" : "+l"(acc[r][1]) : "l"(xv.x), "l"(wv1.x));
                asm("fma.rn.f32x2 %0, %1, %2, %0;" : "+l"(acc[r][2]) : "l"(xv.x), "l"(wv2.x));
                asm("fma.rn.f32x2 %0, %1, %2, %0;" : "+l"(acc[r][3]) : "l"(xv.x), "l"(wv3.x));
                asm("fma.rn.f32x2 %0, %1, %2, %0;" : "+l"(acc[r][0]) : "l"(xv.y), "l"(wv0.y));
                asm("fma.rn.f32x2 %0, %1, %2, %0;" : "+l"(acc[r][1]) : "l"(xv.y), "l"(wv1.y));
                asm("fma.rn.f32x2 %0, %1, %2, %0;" : "+l"(acc[r][2]) : "l"(xv.y), "l"(wv2.y));
                asm("fma.rn.f32x2 %0, %1, %2, %0;" : "+l"(acc[r][3]) : "l"(xv.y), "l"(wv3.y));
            }
        }
    }
    // epilogue 2: out = lo+hi + b2, store live rows
    {
        float4 bv = *(const float4*)&b2[c0];
#pragma unroll
        for (int r = 0; r < 4; r++) {
            if (r0 + r < live) {
                float4 ov;
                ov.x = __uint_as_float((unsigned)acc[r][0]) + __uint_as_float((unsigned)(acc[r][0] >> 32)) + bv.x;
                ov.y = __uint_as_float((unsigned)acc[r][1]) + __uint_as_float((unsigned)(acc[r][1] >> 32)) + bv.y;
                ov.z = __uint_as_float((unsigned)acc[r][2]) + __uint_as_float((unsigned)(acc[r][2] >> 32)) + bv.z;
                ov.w = __uint_as_float((unsigned)acc[r][3]) + __uint_as_float((unsigned)(acc[r][3] >> 32)) + bv.w;
                *(float4*)&out[(size_t)gr4[r] * DD + c0] = ov;
            }
        }
    }
}

// ---------------------------------------------------------------------------
extern "C" void kernel_launch(void* const* d_in, const int* in_sizes, int n_in,
                              void* d_out, int out_size)
{
    const float* emb    = (const float*)d_in[0];
    const float* coords = (const float*)d_in[1];
    const int*   mask   = (const int*)d_in[2];
    const float* W1     = (const float*)d_in[3];
    const float* b1     = (const float*)d_in[4];
    const float* W2     = (const float*)d_in[5];
    const float* b2     = (const float*)d_in[6];

    float* out = (float*)d_out;
    const int tok_elems = BB * AA * DD;
    float* out_mask = (out_size >= tok_elems + BB * AA)     ? out + tok_elems           : nullptr;
    float* out_a2g  = (out_size >= tok_elems + 2 * BB * AA) ? out + tok_elems + BB * AA : nullptr;

    const int smem_scan = AA * 33 * 4 + 2 * AA * 4 + 3 * 32 * 4 + 2 * 33 * 4
                        + 32 * 4 + 1024 * 4;                                   // 148,232
    const int smem_mlp  = (16384 + 16384 + TMR * DD) * 4;                      // 163,840

    cudaFuncSetAttribute(scan_kernel,
                         cudaFuncAttributeMaxDynamicSharedMemorySize, smem_scan);
    cudaFuncSetAttribute(mlp_fill_kernel,
                         cudaFuncAttributeMaxDynamicSharedMemorySize, smem_mlp);

    adjc_kernel<<<dim3(8, BB), 1024>>>(coords, mask);
    scan_kernel<<<BB, 1024, smem_scan>>>(mask, b1, W2, b2, out_mask, out_a2g);
    mlp_fill_kernel<<<(BB * AA) / TMR, 512, smem_mlp>>>(emb, W1, b1, W2, b2, out);
}

// round 17
// speedup vs baseline: 1.3130x; 1.0884x over previous
#include <cuda_runtime.h>
#include <cstdint>

#define BB 32
#define AA 1024
#define DD 128
#define THR2 0.0025f
#define TMR 64   // MLP rows per block

typedef unsigned long long u64;

// Scratch (allocation-free rule: __device__ globals)
__device__ int      g_cnt[BB * AA];          // per-(batch,group) member counts
__device__ uint32_t g_adj[BB * AA * 32];     // COMPACTED proximity bitmatrix (lower triangle only)
__device__ int      g_goff[BB * AA];         // per-(batch,group) member-list offset
__device__ int      g_memlist[BB * AA + 8];  // agents counting-sorted by (batch,group); +8 pad
__device__ int      g_ng[BB];                // groups per batch
__device__ float    g_cfill[DD];             // constant row gelu(b1)@W2 + b2

__device__ __forceinline__ float gelu_exact(float x) {
    return 0.5f * x * (1.0f + erff(x * 0.70710678118654752f));
}

// ---------------------------------------------------------------------------
// Kernel 1: COMPACTED adjacency — lower triangle, LOAD-BALANCED rows.
// grid (8, BB). Warp w of block x owns rows {8*(w+32r)+x : r=0..3} and loops
// each row only to its own wmax = row>>5: every warp's word-total ~equal
// (critical path = avg, not max). Block (0,0) also computes g_cfill.
// ---------------------------------------------------------------------------
__global__ __launch_bounds__(1024, 1)
void adjc_kernel(const float* __restrict__ coords, const int* __restrict__ mask,
                 const float* __restrict__ b1, const float* __restrict__ W2,
                 const float* __restrict__ b2)
{
    __shared__ float2   scc[AA];     // compacted coords
    __shared__ uint32_t svw[32];     // validity words
    __shared__ int      spre[33];    // exclusive prefix of valid counts
    __shared__ float    spart[1024]; // cfill partials (block (0,0) only)
    __shared__ int      s_nv;

    const int b   = blockIdx.y;
    const int bx  = blockIdx.x;
    const int tid = threadIdx.x;
    const int w   = tid >> 5;
    const int l   = tid & 31;

    // prefetch both global reads up front (latencies overlap)
    const int    v = (mask[(size_t)b * AA + tid] != 0);
    const float2 c = ((const float2*)coords)[(size_t)b * AA + tid];
    {
        unsigned m = __ballot_sync(0xffffffffu, v);
        if (l == 0) svw[w] = m;
    }
    __syncthreads();
    if (tid < 32) {
        int cc = __popc(svw[tid]);
        int x = cc;
#pragma unroll
        for (int o = 1; o < 32; o <<= 1) {
            int y = __shfl_up_sync(0xffffffffu, x, o);
            if (tid >= o) x += y;
        }
        spre[tid] = x - cc;
        if (tid == 31) s_nv = x;
    }
    __syncthreads();
    const int nv = s_nv;

    // scatter valid coords to compacted slots (coords already in regs)
    if (v) {
        int cp = spre[w] + __popc(svw[w] & ((1u << l) - 1));
        scc[cp] = c;
    }
    __syncthreads();

    const u64* scc64 = (const u64*)scc;
#pragma unroll 1
    for (int r = 0; r < 4; r++) {
        const int row = 8 * (w + 32 * r) + bx;      // lane-uniform
        if (row >= nv) continue;                    // warp-uniform branch
        const u64 ci = scc64[row];
        const int wmax = row >> 5;                  // lower triangle only
        uint32_t* dst = g_adj + ((size_t)(b * AA) + row) * 32;
        for (int word = 0; word <= wmax; word++) {
            // -cj via sign-bit flip: a + (-b) == a - b exactly (IEEE)
            const u64 ncj = scc64[(word << 5) + l] ^ 0x8000000080000000ULL;
            u64 dp, sq;
            asm("add.rn.f32x2 %0, %1, %2;" : "=l"(dp) : "l"(ci), "l"(ncj));
            asm("mul.rn.f32x2 %0, %1, %2;" : "=l"(sq) : "l"(dp), "l"(dp));
            float lo = __uint_as_float((unsigned)sq);
            float hi = __uint_as_float((unsigned)(sq >> 32));
            unsigned m = __ballot_sync(0xffffffffu, (lo + hi) < THR2);
            if (l == 0) dst[word] = m;
        }
    }

    // ---- block (0,0): constant fill row gelu(b1)@W2 + b2 -> g_cfill ----
    if (b == 0 && bx == 0) {
        const int col = tid & 127;
        const int kq  = tid >> 7;          // 8 k-parts of 16
        float s = 0.f;
        const int kb = kq * 16;
#pragma unroll
        for (int k = 0; k < 16; k++)
            s = fmaf(gelu_exact(b1[kb + k]), W2[(kb + k) * DD + col], s);
        spart[kq * 128 + col] = s;
        __syncthreads();                   // block-uniform branch -> safe
        if (tid < DD) {
            float acc = b2[tid];
#pragma unroll
            for (int q = 0; q < 8; q++) acc += spart[q * 128 + tid];
            g_cfill[tid] = acc;
        }
    }
}

// ---------------------------------------------------------------------------
// Kernel 2: parallel wavefront clustering (32 blocks x 1024 threads).
// [R16 core unchanged; cfill moved out]
// ---------------------------------------------------------------------------
__global__ __launch_bounds__(1024, 1)
void scan_kernel(const int* __restrict__ mask,
                 float* __restrict__ out_mask,   // may be null
                 float* __restrict__ out_a2g)    // may be null
{
    extern __shared__ unsigned char sraw[];
    uint32_t* adj    = (uint32_t*)sraw;             // AA*33 (padded rows)
    int*      s_cnt  = (int*)(adj + AA * 33);       // AA
    int*      s_goff = s_cnt + AA;                  // AA
    uint32_t* svw    = (uint32_t*)(s_goff + AA);    // 32
    uint32_t* sS     = svw + 32;                    // 32 starter bits (compacted)
    uint32_t* sR     = sS + 32;                     // 32 resolved bits (compacted)
    int*      spre   = (int*)(sR + 32);             // 33 valid prefix
    int*      sSp    = spre + 33;                   // 33 starter prefix
    int*      s_wtot = sSp + 33;                    // 32 warp totals
    __shared__ int s_nres, s_nv, s_ng;

    const int b   = blockIdx.x;
    const int tid = threadIdx.x;
    const int w   = tid >> 5;
    const int l   = tid & 31;

    const int v = (mask[(size_t)b * AA + tid] != 0);
    {
        unsigned m = __ballot_sync(0xffffffffu, v);
        if (l == 0) svw[w] = m;
    }
    if (tid == 0) s_nres = 0;
    __syncthreads();
    if (tid < 32) {
        int c = __popc(svw[tid]);
        int x = c;
#pragma unroll
        for (int o = 1; o < 32; o <<= 1) {
            int y = __shfl_up_sync(0xffffffffu, x, o);
            if (tid >= o) x += y;
        }
        spre[tid] = x - c;
        if (tid == 31) s_nv = x;
        sS[tid] = 0;
    }
    __syncthreads();
    const int nv = s_nv;

    if (tid < 32) {   // resolved-init: nonexistent compacted slots are resolved
        int rem = nv - (tid << 5);
        unsigned occ = rem >= 32 ? 0xffffffffu : (rem > 0 ? ((1u << rem) - 1) : 0u);
        sR[tid] = ~occ;
    }
    // bulk load compacted adjacency rows [0, nv) into PADDED layout (33/row).
    // Only quads inside the lower triangle (quad <= row>>7) are read/written.
    {
        const uint4* src = (const uint4*)(g_adj + (size_t)b * AA * 32);
        const int tot = nv * 8;
        for (int i = tid; i < tot; i += 1024) {
            if (((i & 7) << 7) <= (i >> 3)) {      // quad*4 <= row>>5
                uint4 v4 = src[i];
                uint32_t* d = adj + (i >> 3) * 33 + ((i & 7) << 2);
                d[0] = v4.x; d[1] = v4.y; d[2] = v4.z; d[3] = v4.w;
            }
        }
    }
    __syncthreads();

    // ---- wavefront: thread tid = compacted agent tid (if < nv) ----
    const bool active = (tid < nv);
    const unsigned ebits = (1u << l) - 1;
    unsigned wm = 0;                       // words with earlier neighbors
    if (active) {
        for (int k = 0; k <= w; k++) {
            unsigned a = adj[tid * 33 + k];
            if (k == w) a &= ebits;
            if (a) wm |= 1u << k;
        }
    }
    bool resolved = !active;
    while (true) {
        bool decR = false, decS = false;
        if (!resolved) {
            bool blocked = false, pend = false;
            unsigned t = wm;
            while (t) {
                int k = __ffs(t) - 1;
                t &= t - 1u;
                unsigned a = adj[tid * 33 + k];
                if (k == w) a &= ebits;
                if (a & sS[k]) { blocked = true; break; }
                if (a & ~sR[k]) pend = true;
            }
            if (blocked)      decR = true;
            else if (!pend) { decS = true; decR = true; }
        }
        __syncthreads();   // snapshot reads complete
        unsigned smw = __ballot_sync(0xffffffffu, decS);
        unsigned rmw = __ballot_sync(0xffffffffu, decR);
        if (l == 0 && smw) sS[w] |= smw;
        if (l == 0 && rmw) { sR[w] |= rmw; atomicAdd(&s_nres, __popc(rmw)); }
        if (decR) resolved = true;
        __syncthreads();   // writes visible
        if (s_nres >= nv) break;
    }

    // starter prefix (rank -> group id)
    if (tid < 32) {
        int c = __popc(sS[tid]);
        int x = c;
#pragma unroll
        for (int o = 1; o < 32; o <<= 1) {
            int y = __shfl_up_sync(0xffffffffu, x, o);
            if (tid >= o) x += y;
        }
        sSp[tid] = x - c;
        if (tid == 31) s_ng = x;
    }
    __syncthreads();

    // asg for ORIGINAL agents: rank of first starter in (compacted row & S)
    int asg = -1;
    if (v) {
        int cp = spre[w] + __popc(svw[w] & ebits);
        int cw = cp >> 5;
        for (int k = 0; k <= cw; k++) {
            unsigned m2 = adj[cp * 33 + k] & sS[k];
            if (m2) {
                int bit = __ffs(m2) - 1;
                asg = sSp[k] + __popc(sS[k] & ((1u << bit) - 1));
                break;
            }
        }
    }
    const int ng = s_ng;

    // ---- member masks via atomicOr into transposed table in dead adj smem --
    __syncthreads();                 // all adj reads done; reuse region
    uint32_t* sMembT = (uint32_t*)sraw;   // [32][1024]: sMembT[w*1024+g]
#pragma unroll
    for (int k = 0; k < 32; k++) sMembT[k * 1024 + tid] = 0;   // conflict-free
    __syncthreads();
    if (v) atomicOr(&sMembT[w * 1024 + asg], 1u << l);         // spread addrs
    __syncthreads();

    // counts: thread tid = group tid (zero for non-groups); conflict-free
    {
        int cnt = 0;
#pragma unroll
        for (int k = 0; k < 32; k++) cnt += __popc(sMembT[k * 1024 + tid]);
        s_cnt[tid] = cnt;
    }
    __syncthreads();

    // ---- exclusive prefix of counts -> s_goff ----
    {
        int val = s_cnt[tid];
        int x = val;
#pragma unroll
        for (int o = 1; o < 32; o <<= 1) {
            int y = __shfl_up_sync(0xffffffffu, x, o);
            if (l >= o) x += y;
        }
        if (l == 31) s_wtot[w] = x;
        __syncthreads();
        if (tid < 32) {
            int cc = s_wtot[tid];
            int y = cc;
#pragma unroll
            for (int o = 1; o < 32; o <<= 1) {
                int z = __shfl_up_sync(0xffffffffu, y, o);
                if (tid >= o) y += z;
            }
            s_wtot[tid] = y - cc;    // exclusive warp offsets
        }
        __syncthreads();
        s_goff[tid] = x - val + s_wtot[w];
    }
    __syncthreads();

    // ---- counting-sorted member list (ascending agent order per group) ----
    if (v) {
        int rank = __popc(sMembT[w * 1024 + asg] & ebits);
        for (int ww = 0; ww < w; ww++) rank += __popc(sMembT[ww * 1024 + asg]);
        g_memlist[b * AA + s_goff[asg] + rank] = tid;
    }

    // emit
    g_cnt[(size_t)b * AA + tid]  = s_cnt[tid];
    g_goff[(size_t)b * AA + tid] = s_goff[tid];
    if (out_a2g)  out_a2g[(size_t)b * AA + tid]  = (float)asg;
    if (out_mask) out_mask[(size_t)b * AA + tid] = (tid < ng) ? 1.0f : 0.0f;
    if (tid == 0) g_ng[b] = ng;
}

// ---------------------------------------------------------------------------
// Kernel 3: sparse MLP + fill broadcast. [R16 winner — unchanged]
// ---------------------------------------------------------------------------
__global__ __launch_bounds__(512, 1)
void mlp_fill_kernel(const float* __restrict__ emb,
                     const float* __restrict__ W1, const float* __restrict__ b1,
                     const float* __restrict__ W2, const float* __restrict__ b2,
                     float* __restrict__ out)
{
    extern __shared__ float sm[];
    float* sW1T = sm;                  // 16384 floats (4096 float4 slots)
    float* sW2T = sm + 16384;          // 16384
    float* sx   = sm + 32768;          // TMR*DD = 8192

    const int tid  = threadIdx.x;
    const int win  = blockIdx.x;
    const int bb   = win >> 4;              // 16 windows per batch
    const int k0   = (win & 15) * TMR;
    const int ng   = g_ng[bb];
    int live = ng - k0;
    if (live > TMR) live = TMR;
    const int base = win * TMR;             // == bb*AA + k0

    if (live <= 0) {
        // fill-only: every row in this window is empty — broadcast g_cfill
        const int col = tid & 127;
        const float cf = g_cfill[col];
        for (int r = tid >> 7; r < TMR; r += 4)
            out[(size_t)(base + r) * DD + col] = cf;
        return;
    }

    const int wp   = tid >> 5;
    const int lane = tid & 31;
    const int r0   = wp * 4;        // 4 rows per warp (16 warps * 4 = 64)
    const int c0   = lane * 4;      // 4 cols per lane
    const int swl  = lane & 7;

    // ---- GATHER FIRST: mean over contiguous member list (globals only) ----
    int gr4[4], cnt4[4], off4[4];
#pragma unroll
    for (int rr = 0; rr < 4; rr++) {
        int rc = r0 + rr;
        if (rc > live - 1) rc = live - 1;
        gr4[rr]  = base + rc;
        cnt4[rr] = g_cnt[gr4[rr]];
        off4[rr] = g_goff[gr4[rr]];        // independent LDGs (overlap)
    }
    const float* ebase = emb + (size_t)bb * AA * DD;
    const int*   mlb   = g_memlist + (size_t)bb * AA;
#pragma unroll 1
    for (int rr = 0; rr < 4; rr++) {
        const int cnt = cnt4[rr];
        const int* ml = mlb + off4[rr];
        float4 a4 = make_float4(0.f, 0.f, 0.f, 0.f);
        int j = 0;
        for (; j + 4 <= cnt; j += 4) {
            int i0 = ml[j], i1 = ml[j + 1], i2 = ml[j + 2], i3 = ml[j + 3];
            float4 v0 = *((const float4*)(ebase + (size_t)i0 * DD) + lane);
            float4 v1 = *((const float4*)(ebase + (size_t)i1 * DD) + lane);
            float4 v2 = *((const float4*)(ebase + (size_t)i2 * DD) + lane);
            float4 v3 = *((const float4*)(ebase + (size_t)i3 * DD) + lane);
            a4.x += (v0.x + v1.x) + (v2.x + v3.x);
            a4.y += (v0.y + v1.y) + (v2.y + v3.y);
            a4.z += (v0.z + v1.z) + (v2.z + v3.z);
            a4.w += (v0.w + v1.w) + (v2.w + v3.w);
        }
        int rem = cnt - j;
        if (rem > 0) {
            // overreads hit zero-init pad / other entries: values in [0, AA),
            // so the row loads are safe; contributions gated.
            int i0 = ml[j], i1 = ml[j + 1], i2 = ml[j + 2];
            float f1 = rem > 1 ? 1.f : 0.f;
            float f2 = rem > 2 ? 1.f : 0.f;
            float4 v0 = *((const float4*)(ebase + (size_t)i0 * DD) + lane);
            float4 v1 = *((const float4*)(ebase + (size_t)i1 * DD) + lane);
            float4 v2 = *((const float4*)(ebase + (size_t)i2 * DD) + lane);
            a4.x += v0.x + f1 * v1.x + f2 * v2.x;
            a4.y += v0.y + f1 * v1.y + f2 * v2.y;
            a4.z += v0.z + f1 * v1.z + f2 * v2.z;
            a4.w += v0.w + f1 * v1.w + f2 * v2.w;
        }
        float inv = 1.0f / (float)(cnt > 1 ? cnt : 1);
        a4.x *= inv; a4.y *= inv; a4.z *= inv; a4.w *= inv;
        *(float4*)&sx[(r0 + rr) * DD + c0] = a4;
    }

    // ---- weight staging: slot(c,g) = c*32 + (g ^ ((c>>2)&7)), conflict-free
    {
        float4* w1t = (float4*)sW1T;
        float4* w2t = (float4*)sW2T;
#pragma unroll
        for (int it = 0; it < 8; it++) {
            int i = tid + it * 512;
            int c = ((i & 31) << 2) | ((i >> 5) & 3);
            int g = i >> 7;
            int slot = c * 32 + (g ^ ((c >> 2) & 7));
            float4 v1, v2;
            v1.x = W1[(4 * g + 0) * DD + c];
            v1.y = W1[(4 * g + 1) * DD + c];
            v1.z = W1[(4 * g + 2) * DD + c];
            v1.w = W1[(4 * g + 3) * DD + c];
            v2.x = W2[(4 * g + 0) * DD + c];
            v2.y = W2[(4 * g + 1) * DD + c];
            v2.z = W2[(4 * g + 2) * DD + c];
            v2.w = W2[(4 * g + 3) * DD + c];
            w1t[slot] = v1;
            w2t[slot] = v2;
        }
    }
    __syncthreads();

    // boundary fill: rows [live, TMR) of this window are empty
    if (live < TMR && tid < DD) {
        float cf = g_cfill[tid];
        for (int r = live; r < TMR; r++)
            out[(size_t)(base + r) * DD + tid] = cf;
    }

    u64 acc[4][4];

    // ================= layer 1 =================
#pragma unroll
    for (int r = 0; r < 4; r++)
#pragma unroll
        for (int cc = 0; cc < 4; cc++) acc[r][cc] = 0ull;

    {
        const ulonglong2* wp4 = (const ulonglong2*)sW1T;
#pragma unroll 4
        for (int g = 0; g < 32; g++) {
            const int gs = g ^ swl;
            ulonglong2 wv0 = wp4[(c0 + 0) * 32 + gs];
            ulonglong2 wv1 = wp4[(c0 + 1) * 32 + gs];
            ulonglong2 wv2 = wp4[(c0 + 2) * 32 + gs];
            ulonglong2 wv3 = wp4[(c0 + 3) * 32 + gs];
#pragma unroll
            for (int r = 0; r < 4; r++) {
                ulonglong2 xv = *(const ulonglong2*)(sx + (r0 + r) * DD + 4 * g);
                asm("fma.rn.f32x2 %0, %1, %2, %0;" : "+l"(acc[r][0]) : "l"(xv.x), "l"(wv0.x));
                asm("fma.rn.f32x2 %0, %1, %2, %0;" : "+l"(acc[r][1]) : "l"(xv.x), "l"(wv1.x));
                asm("fma.rn.f32x2 %0, %1, %2, %0;" : "+l"(acc[r][2]) : "l"(xv.x), "l"(wv2.x));
                asm("fma.rn.f32x2 %0, %1, %2, %0;" : "+l"(acc[r][3]) : "l"(xv.x), "l"(wv3.x));
                asm("fma.rn.f32x2 %0, %1, %2, %0;" : "+l"(acc[r][0]) : "l"(xv.y), "l"(wv0.y));
                asm("fma.rn.f32x2 %0, %1, %2, %0;" : "+l"(acc[r][1]) : "l"(xv.y), "l"(wv1.y));
                asm("fma.rn.f32x2 %0, %1, %2, %0;" : "+l"(acc[r][2]) : "l"(xv.y), "l"(wv2.y));
                asm("fma.rn.f32x2 %0, %1, %2, %0;" : "+l"(acc[r][3]) : "l"(xv.y), "l"(wv3.y));
            }
        }
    }
    // epilogue 1: h = gelu(lo+hi + b1); warp owns its rows -> no barrier
    {
        float4 bv = *(const float4*)&b1[c0];
#pragma unroll
        for (int r = 0; r < 4; r++) {
            float4 h;
            h.x = gelu_exact(__uint_as_float((unsigned)acc[r][0]) + __uint_as_float((unsigned)(acc[r][0] >> 32)) + bv.x);
            h.y = gelu_exact(__uint_as_float((unsigned)acc[r][1]) + __uint_as_float((unsigned)(acc[r][1] >> 32)) + bv.y);
            h.z = gelu_exact(__uint_as_float((unsigned)acc[r][2]) + __uint_as_float((unsigned)(acc[r][2] >> 32)) + bv.z);
            h.w = gelu_exact(__uint_as_float((unsigned)acc[r][3]) + __uint_as_float((unsigned)(acc[r][3] >> 32)) + bv.w);
            *(float4*)&sx[(r0 + r) * DD + c0] = h;
        }
    }
    __syncwarp();

    // ================= layer 2 =================
#pragma unroll
    for (int r = 0; r < 4; r++)
#pragma unroll
        for (int cc = 0; cc < 4; cc++) acc[r][cc] = 0ull;

    {
        const ulonglong2* wp4 = (const ulonglong2*)sW2T;
#pragma unroll 4
        for (int g = 0; g < 32; g++) {
            const int gs = g ^ swl;
            ulonglong2 wv0 = wp4[(c0 + 0) * 32 + gs];
            ulonglong2 wv1 = wp4[(c0 + 1) * 32 + gs];
            ulonglong2 wv2 = wp4[(c0 + 2) * 32 + gs];
            ulonglong2 wv3 = wp4[(c0 + 3) * 32 + gs];
#pragma unroll
            for (int r = 0; r < 4; r++) {
                ulonglong2 xv = *(const ulonglong2*)(sx + (r0 + r) * DD + 4 * g);
                asm("fma.rn.f32x2 %0, %1, %2, %0;" : "+l"(acc[r][0]) : "l"(xv.x), "l"(wv0.x));
                asm("fma.rn.f32x2 %0, %1, %2, %0;" : "+l"(acc[r][1]) : "l"(xv.x), "l"(wv1.x));
                asm("fma.rn.f32x2 %0, %1, %2, %0;" : "+l"(acc[r][2]) : "l"(xv.x), "l"(wv2.x));
                asm("fma.rn.f32x2 %0, %1, %2, %0;" : "+l"(acc[r][3]) : "l"(xv.x), "l"(wv3.x));
                asm("fma.rn.f32x2 %0, %1, %2, %0;" : "+l"(acc[r][0]) : "l"(xv.y), "l"(wv0.y));
                asm("fma.rn.f32x2 %0, %1, %2, %0;" : "+l"(acc[r][1]) : "l"(xv.y), "l"(wv1.y));
                asm("fma.rn.f32x2 %0, %1, %2, %0;" : "+l"(acc[r][2]) : "l"(xv.y), "l"(wv2.y));
                asm("fma.rn.f32x2 %0, %1, %2, %0;" : "+l"(acc[r][3]) : "l"(xv.y), "l"(wv3.y));
            }
        }
    }
    // epilogue 2: out = lo+hi + b2, store live rows
    {
        float4 bv = *(const float4*)&b2[c0];
#pragma unroll
        for (int r = 0; r < 4; r++) {
            if (r0 + r < live) {
                float4 ov;
                ov.x = __uint_as_float((unsigned)acc[r][0]) + __uint_as_float((unsigned)(acc[r][0] >> 32)) + bv.x;
                ov.y = __uint_as_float((unsigned)acc[r][1]) + __uint_as_float((unsigned)(acc[r][1] >> 32)) + bv.y;
                ov.z = __uint_as_float((unsigned)acc[r][2]) + __uint_as_float((unsigned)(acc[r][2] >> 32)) + bv.z;
                ov.w = __uint_as_float((unsigned)acc[r][3]) + __uint_as_float((unsigned)(acc[r][3] >> 32)) + bv.w;
                *(float4*)&out[(size_t)gr4[r] * DD + c0] = ov;
            }
        }
    }
}

// ---------------------------------------------------------------------------
extern "C" void kernel_launch(void* const* d_in, const int* in_sizes, int n_in,
                              void* d_out, int out_size)
{
    const float* emb    = (const float*)d_in[0];
    const float* coords = (const float*)d_in[1];
    const int*   mask   = (const int*)d_in[2];
    const float* W1     = (const float*)d_in[3];
    const float* b1     = (const float*)d_in[4];
    const float* W2     = (const float*)d_in[5];
    const float* b2     = (const float*)d_in[6];

    float* out = (float*)d_out;
    const int tok_elems = BB * AA * DD;
    float* out_mask = (out_size >= tok_elems + BB * AA)     ? out + tok_elems           : nullptr;
    float* out_a2g  = (out_size >= tok_elems + 2 * BB * AA) ? out + tok_elems + BB * AA : nullptr;

    const int smem_scan = AA * 33 * 4 + 2 * AA * 4 + 3 * 32 * 4 + 2 * 33 * 4 + 32 * 4; // 144,136
    const int smem_mlp  = (16384 + 16384 + TMR * DD) * 4;                              // 163,840

    cudaFuncSetAttribute(scan_kernel,
                         cudaFuncAttributeMaxDynamicSharedMemorySize, smem_scan);
    cudaFuncSetAttribute(mlp_fill_kernel,
                         cudaFuncAttributeMaxDynamicSharedMemorySize, smem_mlp);

    adjc_kernel<<<dim3(8, BB), 1024>>>(coords, mask, b1, W2, b2);
    scan_kernel<<<BB, 1024, smem_scan>>>(mask, out_mask, out_a2g);
    mlp_fill_kernel<<<(BB * AA) / TMR, 512, smem_mlp>>>(emb, W1, b1, W2, b2, out);
}